// round 1
// baseline (speedup 1.0000x reference)
#include <cuda_runtime.h>
#include <cuda_bf16.h>
#include <mma.h>

using namespace nvcuda;

// Problem constants
#define B_SZ   4
#define C_SZ   192
#define H_SZ   256
#define W_SZ   256
#define TOK    (B_SZ * H_SZ * W_SZ)   // 262144 tokens
#define NWIN   (B_SZ * 32 * 32)        // 4096 windows
#define NH_SZ  6
#define HD_SZ  32
#define HID_SZ 768

// -------- scratch (device globals: allocation-free) --------
__device__ __nv_bfloat16 g_xln [(size_t)TOK * C_SZ];
__device__ __nv_bfloat16 g_qkv [(size_t)TOK * 3 * C_SZ];
__device__ __nv_bfloat16 g_attn[(size_t)TOK * C_SZ];
__device__ float         g_y1  [(size_t)TOK * C_SZ];
__device__ __nv_bfloat16 g_hln [(size_t)TOK * C_SZ];
__device__ __nv_bfloat16 g_hid [(size_t)TOK * HID_SZ];
__device__ __nv_bfloat16 g_wq  [3 * C_SZ * C_SZ];
__device__ __nv_bfloat16 g_wp  [C_SZ * C_SZ];
__device__ __nv_bfloat16 g_w1  [HID_SZ * C_SZ];
__device__ __nv_bfloat16 g_w2  [C_SZ * HID_SZ];

// -------- fp32 -> bf16 weight convert --------
__global__ void cvt_kernel(const float* __restrict__ in, __nv_bfloat16* __restrict__ out, int n) {
    int i = blockIdx.x * blockDim.x + threadIdx.x;
    if (i < n) out[i] = __float2bfloat16(in[i]);
}

// -------- LN1 over channels + window-partition reorder --------
// x: (B,C,H,W). token t = ((b*32 + h/8)*32 + w/8)*64 + (h%8)*8 + (w%8)
__global__ __launch_bounds__(256) void ln1_kernel(const float* __restrict__ x,
                                                  const float* __restrict__ w,
                                                  const float* __restrict__ b) {
    int pix = blockIdx.x * blockDim.x + threadIdx.x;   // 0..TOK-1
    int bidx = pix >> 16;
    int hw   = pix & 65535;
    int h    = hw >> 8;
    int wc   = hw & 255;
    const float* xp = x + (size_t)bidx * C_SZ * 65536 + hw;
    float sum = 0.f, sumsq = 0.f;
    #pragma unroll 8
    for (int c = 0; c < C_SZ; c++) {
        float v = xp[(size_t)c * 65536];
        sum += v; sumsq += v * v;
    }
    float mu  = sum * (1.f / C_SZ);
    float var = sumsq * (1.f / C_SZ) - mu * mu;
    float rs  = rsqrtf(var + 1e-5f);
    int t = ((bidx * 32 + (h >> 3)) * 32 + (wc >> 3)) * 64 + ((h & 7) * 8 + (wc & 7));
    __nv_bfloat16* o = g_xln + (size_t)t * C_SZ;
    #pragma unroll 8
    for (int c = 0; c < C_SZ; c++) {
        float v = xp[(size_t)c * 65536];
        o[c] = __float2bfloat16((v - mu) * rs * w[c] + b[c]);
    }
}

// -------- generic 64x64-tile GEMM: C = act(A @ W^T + bias) (+ residual variants) ----
// A: [M,K] bf16 row-major. W: [N,K] bf16 row-major (so W^T is col-major with ld=K).
// MODE 0: bf16 out [M,N]
// MODE 1: exact GELU then bf16 out [M,N]
// MODE 2: fp32 out[m*192+n] = resBCHW[x-gather] + v   (proj + residual)
// MODE 3: outBCHW = res[m*192+n] + v                   (mlp2 + residual, scatter)
template<int MODE>
__global__ __launch_bounds__(256) void gemm_kernel(const __nv_bfloat16* __restrict__ A,
                                                   const __nv_bfloat16* __restrict__ W,
                                                   const float* __restrict__ bias,
                                                   int K, int N,
                                                   void* __restrict__ outp,
                                                   const float* __restrict__ res) {
    __shared__ __align__(16) __nv_bfloat16 As[64 * 16];
    __shared__ __align__(16) __nv_bfloat16 Bs[64 * 16];
    __shared__ float Cs[64 * 68];

    const int n0 = blockIdx.x * 64;
    const int m0 = blockIdx.y * 64;
    const int tid  = threadIdx.x;
    const int warp = tid >> 5;
    const int wr = warp >> 1;      // 0..3 -> row tile
    const int wc = warp & 1;       // 0..1 -> col half

    wmma::fragment<wmma::accumulator, 16, 16, 16, float> acc0, acc1;
    wmma::fill_fragment(acc0, 0.f);
    wmma::fill_fragment(acc1, 0.f);

    for (int k0 = 0; k0 < K; k0 += 16) {
        if (tid < 128) {
            int r = tid >> 1, s = (tid & 1) * 8;
            *(uint4*)(As + r * 16 + s) = *(const uint4*)(A + (size_t)(m0 + r) * K + k0 + s);
        } else {
            int t2 = tid - 128;
            int r = t2 >> 1, s = (t2 & 1) * 8;
            *(uint4*)(Bs + r * 16 + s) = *(const uint4*)(W + (size_t)(n0 + r) * K + k0 + s);
        }
        __syncthreads();

        wmma::fragment<wmma::matrix_a, 16, 16, 16, __nv_bfloat16, wmma::row_major> fa;
        wmma::load_matrix_sync(fa, As + wr * 16 * 16, 16);
        wmma::fragment<wmma::matrix_b, 16, 16, 16, __nv_bfloat16, wmma::col_major> fb;
        wmma::load_matrix_sync(fb, Bs + (wc * 32) * 16, 16);
        wmma::mma_sync(acc0, fa, fb, acc0);
        wmma::load_matrix_sync(fb, Bs + (wc * 32 + 16) * 16, 16);
        wmma::mma_sync(acc1, fa, fb, acc1);
        __syncthreads();
    }

    wmma::store_matrix_sync(Cs + (wr * 16) * 68 + wc * 32,      acc0, 68, wmma::mem_row_major);
    wmma::store_matrix_sync(Cs + (wr * 16) * 68 + wc * 32 + 16, acc1, 68, wmma::mem_row_major);
    __syncthreads();

    for (int idx = tid; idx < 64 * 64; idx += 256) {
        int r, cc;
        if (MODE <= 1) { r = idx >> 6; cc = idx & 63; }
        else           { r = idx & 63; cc = idx >> 6; }
        int m = m0 + r, n = n0 + cc;
        float v = Cs[r * 68 + cc] + bias[n];
        if (MODE == 0) {
            ((__nv_bfloat16*)outp)[(size_t)m * N + n] = __float2bfloat16(v);
        } else if (MODE == 1) {
            v = 0.5f * v * (1.f + erff(v * 0.70710678118654752f));
            ((__nv_bfloat16*)outp)[(size_t)m * N + n] = __float2bfloat16(v);
        } else {
            // token -> (b,h,w)
            int bb   = m >> 16;
            int rem  = m & 65535;
            int wh   = rem >> 11;
            int rem2 = rem & 2047;
            int ww   = rem2 >> 6;
            int nn   = rem2 & 63;
            int h    = wh * 8 + (nn >> 3);
            int wcol = ww * 8 + (nn & 7);
            size_t bchw = (((size_t)bb * C_SZ + n) * H_SZ + h) * W_SZ + wcol;
            if (MODE == 2) {
                ((float*)outp)[(size_t)m * C_SZ + n] = res[bchw] + v;
            } else { // MODE == 3
                ((float*)outp)[bchw] = res[(size_t)m * C_SZ + n] + v;
            }
        }
    }
}

// -------- window attention: one block per (window, head) --------
__global__ __launch_bounds__(256) void attn_kernel() {
    __shared__ float qs[64][33];
    __shared__ float ks[64][33];
    __shared__ float vs[64][33];
    __shared__ float sc[64][65];

    const int win  = blockIdx.x;
    const int head = blockIdx.y;
    const int tid  = threadIdx.x;
    const float scale = 0.17677669529663687f;   // 1/sqrt(32)

    const __nv_bfloat16* base = g_qkv + (size_t)win * 64 * (3 * C_SZ) + head * HD_SZ;
    for (int idx = tid; idx < 64 * 32; idx += 256) {
        int n = idx >> 5, d = idx & 31;
        const __nv_bfloat16* row = base + (size_t)n * (3 * C_SZ) + d;
        qs[n][d] = __bfloat162float(row[0])       * scale;
        ks[n][d] = __bfloat162float(row[C_SZ]);
        vs[n][d] = __bfloat162float(row[2 * C_SZ]);
    }
    __syncthreads();

    for (int idx = tid; idx < 64 * 64; idx += 256) {
        int n = idx >> 6, m = idx & 63;
        float s = 0.f;
        #pragma unroll
        for (int d = 0; d < 32; d++) s += qs[n][d] * ks[m][d];
        sc[n][m] = s;
    }
    __syncthreads();

    const int warp = tid >> 5, lane = tid & 31;
    #pragma unroll
    for (int r = 0; r < 8; r++) {
        int row = warp * 8 + r;
        float v0 = sc[row][lane], v1 = sc[row][lane + 32];
        float mx = fmaxf(v0, v1);
        #pragma unroll
        for (int o = 16; o; o >>= 1) mx = fmaxf(mx, __shfl_xor_sync(0xffffffffu, mx, o));
        float e0 = __expf(v0 - mx), e1 = __expf(v1 - mx);
        float s = e0 + e1;
        #pragma unroll
        for (int o = 16; o; o >>= 1) s += __shfl_xor_sync(0xffffffffu, s, o);
        float inv = 1.f / s;
        sc[row][lane]      = e0 * inv;
        sc[row][lane + 32] = e1 * inv;
    }
    __syncthreads();

    for (int idx = tid; idx < 64 * 32; idx += 256) {
        int n = idx >> 5, d = idx & 31;
        float o = 0.f;
        #pragma unroll
        for (int m = 0; m < 64; m++) o += sc[n][m] * vs[m][d];
        g_attn[(size_t)(win * 64 + n) * C_SZ + head * HD_SZ + d] = __float2bfloat16(o);
    }
}

// -------- LN2: warp per token over fp32 y1 --------
__global__ __launch_bounds__(256) void ln2_kernel(const float* __restrict__ w,
                                                  const float* __restrict__ b) {
    int t    = blockIdx.x * 8 + (threadIdx.x >> 5);
    int lane = threadIdx.x & 31;
    const float* row = g_y1 + (size_t)t * C_SZ;
    float v[6];
    float sum = 0.f;
    #pragma unroll
    for (int i = 0; i < 6; i++) { v[i] = row[lane + i * 32]; sum += v[i]; }
    #pragma unroll
    for (int o = 16; o; o >>= 1) sum += __shfl_xor_sync(0xffffffffu, sum, o);
    float mu = sum * (1.f / C_SZ);
    float sq = 0.f;
    #pragma unroll
    for (int i = 0; i < 6; i++) { float d = v[i] - mu; sq += d * d; }
    #pragma unroll
    for (int o = 16; o; o >>= 1) sq += __shfl_xor_sync(0xffffffffu, sq, o);
    float rs = rsqrtf(sq * (1.f / C_SZ) + 1e-5f);
    __nv_bfloat16* out = g_hln + (size_t)t * C_SZ;
    #pragma unroll
    for (int i = 0; i < 6; i++) {
        int c = lane + i * 32;
        out[c] = __float2bfloat16((v[i] - mu) * rs * w[c] + b[c]);
    }
}

extern "C" void kernel_launch(void* const* d_in, const int* in_sizes, int n_in,
                              void* d_out, int out_size) {
    const float* x     = (const float*)d_in[0];
    const float* n1w   = (const float*)d_in[1];
    const float* n1b   = (const float*)d_in[2];
    const float* qkvw  = (const float*)d_in[3];
    const float* qkvb  = (const float*)d_in[4];
    const float* projw = (const float*)d_in[5];
    const float* projb = (const float*)d_in[6];
    const float* n2w   = (const float*)d_in[7];
    const float* n2b   = (const float*)d_in[8];
    const float* w1    = (const float*)d_in[9];
    const float* b1    = (const float*)d_in[10];
    const float* w2    = (const float*)d_in[11];
    const float* b2    = (const float*)d_in[12];
    float* out = (float*)d_out;

    void *p_xln, *p_qkv, *p_attn, *p_y1, *p_hln, *p_hid, *p_wq, *p_wp, *p_w1, *p_w2;
    cudaGetSymbolAddress(&p_xln, g_xln);
    cudaGetSymbolAddress(&p_qkv, g_qkv);
    cudaGetSymbolAddress(&p_attn, g_attn);
    cudaGetSymbolAddress(&p_y1, g_y1);
    cudaGetSymbolAddress(&p_hln, g_hln);
    cudaGetSymbolAddress(&p_hid, g_hid);
    cudaGetSymbolAddress(&p_wq, g_wq);
    cudaGetSymbolAddress(&p_wp, g_wp);
    cudaGetSymbolAddress(&p_w1, g_w1);
    cudaGetSymbolAddress(&p_w2, g_w2);

    // weight conversion (idempotent)
    cvt_kernel<<<(3*C_SZ*C_SZ + 255)/256, 256>>>(qkvw, (__nv_bfloat16*)p_wq, 3*C_SZ*C_SZ);
    cvt_kernel<<<(C_SZ*C_SZ + 255)/256, 256>>>(projw, (__nv_bfloat16*)p_wp, C_SZ*C_SZ);
    cvt_kernel<<<(HID_SZ*C_SZ + 255)/256, 256>>>(w1, (__nv_bfloat16*)p_w1, HID_SZ*C_SZ);
    cvt_kernel<<<(C_SZ*HID_SZ + 255)/256, 256>>>(w2, (__nv_bfloat16*)p_w2, C_SZ*HID_SZ);

    // 1) LN1 + window partition
    ln1_kernel<<<TOK/256, 256>>>(x, n1w, n1b);

    // 2) QKV GEMM: [TOK,192] x [576,192]^T -> bf16 [TOK,576]
    gemm_kernel<0><<<dim3(9, TOK/64), 256>>>((const __nv_bfloat16*)p_xln,
                                             (const __nv_bfloat16*)p_wq,
                                             qkvb, C_SZ, 3*C_SZ, p_qkv, nullptr);

    // 3) window attention
    attn_kernel<<<dim3(NWIN, NH_SZ), 256>>>();

    // 4) proj GEMM + residual (gather x from BCHW) -> fp32 y1 [TOK,192]
    gemm_kernel<2><<<dim3(3, TOK/64), 256>>>((const __nv_bfloat16*)p_attn,
                                             (const __nv_bfloat16*)p_wp,
                                             projb, C_SZ, C_SZ, p_y1, x);

    // 5) LN2
    ln2_kernel<<<TOK/8, 256>>>(n2w, n2b);

    // 6) MLP1 + GELU -> bf16 [TOK,768]
    gemm_kernel<1><<<dim3(12, TOK/64), 256>>>((const __nv_bfloat16*)p_hln,
                                              (const __nv_bfloat16*)p_w1,
                                              b1, C_SZ, HID_SZ, p_hid, nullptr);

    // 7) MLP2 + residual -> scatter to BCHW output
    gemm_kernel<3><<<dim3(3, TOK/64), 256>>>((const __nv_bfloat16*)p_hid,
                                             (const __nv_bfloat16*)p_w2,
                                             b2, HID_SZ, C_SZ, out, (const float*)p_y1);
}

// round 2
// speedup vs baseline: 1.8174x; 1.8174x over previous
#include <cuda_runtime.h>
#include <cuda_bf16.h>
#include <mma.h>

using namespace nvcuda;

#define B_SZ   4
#define C_SZ   192
#define H_SZ   256
#define W_SZ   256
#define TOK    (B_SZ * H_SZ * W_SZ)   // 262144
#define NWIN   (B_SZ * 32 * 32)       // 4096
#define NH_SZ  6
#define HID_SZ 768

// -------- scratch (device globals) --------
__device__ __nv_bfloat16 g_xln [(size_t)TOK * C_SZ];
__device__ float         g_xres[(size_t)TOK * C_SZ];
__device__ __nv_bfloat16 g_qkv [(size_t)TOK * 3 * C_SZ];
__device__ __nv_bfloat16 g_attn[(size_t)TOK * C_SZ];
__device__ float         g_y1  [(size_t)TOK * C_SZ];
__device__ __nv_bfloat16 g_hln [(size_t)TOK * C_SZ];
__device__ __nv_bfloat16 g_hid [(size_t)TOK * HID_SZ];
__device__ __nv_bfloat16 g_wq  [3 * C_SZ * C_SZ];
__device__ __nv_bfloat16 g_wp  [C_SZ * C_SZ];
__device__ __nv_bfloat16 g_w1  [HID_SZ * C_SZ];
__device__ __nv_bfloat16 g_w2  [C_SZ * HID_SZ];

// -------- helpers --------
__device__ __forceinline__ unsigned smem_u32(const void* p) {
    return (unsigned)__cvta_generic_to_shared(p);
}
__device__ __forceinline__ void cp16(void* s, const void* g) {
    asm volatile("cp.async.cg.shared.global [%0], [%1], 16;\n"
                 :: "r"(smem_u32(s)), "l"(g));
}
#define CP_COMMIT asm volatile("cp.async.commit_group;\n" ::: "memory")
#define CP_WAIT(N) asm volatile("cp.async.wait_group %0;\n" :: "n"(N) : "memory")

// -------- fp32 -> bf16 weight convert --------
__global__ void cvt_kernel(const float* __restrict__ in, __nv_bfloat16* __restrict__ out, int n) {
    int i = blockIdx.x * blockDim.x + threadIdx.x;
    if (i < n) out[i] = __float2bfloat16(in[i]);
}

// -------- LN1: single pass over x (BCHW), emits token-major bf16 (g_xln) + fp32 copy (g_xres)
// 32 tokens (consecutive raster pixels) per block.
__global__ __launch_bounds__(256) void ln1_kernel(const float* __restrict__ x,
                                                  const float* __restrict__ w,
                                                  const float* __restrict__ b) {
    __shared__ float xs[32 * 193];
    __shared__ float smu[32], srs[32];
    const int tid = threadIdx.x;
    const int pix0 = blockIdx.x * 32;
    const int bidx = pix0 >> 16;
    const int hw0  = pix0 & 65535;
    const float* xb = x + (size_t)bidx * C_SZ * 65536 + hw0;

    // load: 192 channels x 32 pixels, coalesced per channel
    #pragma unroll 6
    for (int i = tid; i < 32 * 192; i += 256) {
        int c = i >> 5, p = i & 31;
        xs[p * 193 + c] = xb[(size_t)c * 65536 + p];
    }
    __syncthreads();

    // stats: 2 threads per token
    if (tid < 64) {
        int t = tid >> 1, h = tid & 1;
        const float* row = xs + t * 193 + h * 96;
        float s = 0.f, sq = 0.f;
        #pragma unroll 8
        for (int j = 0; j < 96; j++) { float v = row[j]; s += v; sq += v * v; }
        s  += __shfl_xor_sync(0xffffffffu, s, 1);
        sq += __shfl_xor_sync(0xffffffffu, sq, 1);
        if (h == 0) {
            float mu = s * (1.f / C_SZ);
            smu[t] = mu;
            srs[t] = rsqrtf(sq * (1.f / C_SZ) - mu * mu + 1e-5f);
        }
    }
    __syncthreads();

    // write: token-major, coalesced
    #pragma unroll 6
    for (int i = tid; i < 32 * 192; i += 256) {
        int p = i / 192, c = i - p * 192;
        float v = xs[p * 193 + c];
        size_t off = (size_t)(pix0 + p) * C_SZ + c;
        g_xres[off] = v;
        g_xln[off]  = __float2bfloat16((v - smu[p]) * srs[p] * w[c] + b[c]);
    }
}

// -------- pipelined 128x64 GEMM: out = act(A @ W^T + bias) (+ residual variants)
// A [M,K] bf16 row-major, W [N,K] bf16 row-major.
// MODE 0: bf16 out [M,N]
// MODE 1: GELU(exact) -> bf16 out [M,N]
// MODE 2: fp32 out[m*192+n] = res[m*192+n] + v            (proj + residual, token-major)
// MODE 3: outBCHW[b,n,h,w] = res[m*192+n] + v             (mlp2 + residual, coalesced BCHW)
template<int MODE>
__global__ __launch_bounds__(256) void gemm128(const __nv_bfloat16* __restrict__ A,
                                               const __nv_bfloat16* __restrict__ W,
                                               const float* __restrict__ bias,
                                               int K, int N,
                                               void* __restrict__ outp,
                                               const float* __restrict__ res) {
    __shared__ __align__(16) unsigned char sbuf[36864];
    const int m0 = blockIdx.y * 128;
    const int n0 = blockIdx.x * 64;
    const int tid = threadIdx.x;
    const int warp = tid >> 5, lane = tid & 31;
    const int wm = warp >> 1, wn = warp & 1;

    wmma::fragment<wmma::accumulator, 16, 16, 16, float> a00, a01, a10, a11;
    wmma::fill_fragment(a00, 0.f); wmma::fill_fragment(a01, 0.f);
    wmma::fill_fragment(a10, 0.f); wmma::fill_fragment(a11, 0.f);

    auto load_stage = [&](int st, int kk) {
        __nv_bfloat16* as = (__nv_bfloat16*)(sbuf + st * 12288);
        __nv_bfloat16* bs = as + 128 * 32;
        #pragma unroll
        for (int it = 0; it < 2; it++) {
            int u = tid + it * 256;
            int row = u >> 2, q = u & 3;
            cp16(as + row * 32 + q * 8, A + (size_t)(m0 + row) * K + kk + q * 8);
        }
        { int row = tid >> 2, q = tid & 3;
          cp16(bs + row * 32 + q * 8, W + (size_t)(n0 + row) * K + kk + q * 8); }
    };

    const int nst = K >> 5;
    load_stage(0, 0); CP_COMMIT;
    for (int s = 0; s < nst; s++) {
        if (s + 1 < nst) { load_stage((s + 1) & 1, (s + 1) * 32); CP_COMMIT; CP_WAIT(1); }
        else             { CP_WAIT(0); }
        __syncthreads();
        const __nv_bfloat16* as = (const __nv_bfloat16*)(sbuf + (s & 1) * 12288);
        const __nv_bfloat16* bs = as + 128 * 32;
        #pragma unroll
        for (int ks = 0; ks < 2; ks++) {
            wmma::fragment<wmma::matrix_a, 16, 16, 16, __nv_bfloat16, wmma::row_major> fa0, fa1;
            wmma::fragment<wmma::matrix_b, 16, 16, 16, __nv_bfloat16, wmma::col_major> fb0, fb1;
            wmma::load_matrix_sync(fa0, as + (wm * 32) * 32 + ks * 16, 32);
            wmma::load_matrix_sync(fa1, as + (wm * 32 + 16) * 32 + ks * 16, 32);
            wmma::load_matrix_sync(fb0, bs + (wn * 32) * 32 + ks * 16, 32);
            wmma::load_matrix_sync(fb1, bs + (wn * 32 + 16) * 32 + ks * 16, 32);
            wmma::mma_sync(a00, fa0, fb0, a00);
            wmma::mma_sync(a01, fa0, fb1, a01);
            wmma::mma_sync(a10, fa1, fb0, a10);
            wmma::mma_sync(a11, fa1, fb1, a11);
        }
        __syncthreads();
    }

    // per-warp epilogue staging (reuses stage smem; all warps past last barrier)
    float* Ep = (float*)sbuf + warp * (32 * 36);
    wmma::store_matrix_sync(Ep,            a00, 36, wmma::mem_row_major);
    wmma::store_matrix_sync(Ep + 16,       a01, 36, wmma::mem_row_major);
    wmma::store_matrix_sync(Ep + 16 * 36,  a10, 36, wmma::mem_row_major);
    wmma::store_matrix_sync(Ep + 16 * 36 + 16, a11, 36, wmma::mem_row_major);
    __syncwarp();

    const int n = n0 + wn * 32 + lane;
    const float bn = bias[n];

    if (MODE == 0) {
        #pragma unroll 8
        for (int r = 0; r < 32; r++) {
            float v = Ep[r * 36 + lane] + bn;
            ((__nv_bfloat16*)outp)[(size_t)(m0 + wm * 32 + r) * N + n] = __float2bfloat16(v);
        }
    } else if (MODE == 1) {
        #pragma unroll 4
        for (int r = 0; r < 32; r++) {
            float v = Ep[r * 36 + lane] + bn;
            v = 0.5f * v * (1.f + erff(v * 0.70710678118654752f));
            ((__nv_bfloat16*)outp)[(size_t)(m0 + wm * 32 + r) * N + n] = __float2bfloat16(v);
        }
    } else if (MODE == 2) {
        #pragma unroll 8
        for (int r = 0; r < 32; r++) {
            size_t off = (size_t)(m0 + wm * 32 + r) * C_SZ + n;
            ((float*)outp)[off] = res[off] + Ep[r * 36 + lane] + bn;
        }
    } else { // MODE 3
        #pragma unroll 8
        for (int r = 0; r < 32; r++) {
            size_t off = (size_t)(m0 + wm * 32 + r) * C_SZ + n;
            Ep[r * 36 + lane] += bn + res[off];
        }
        __syncwarp();
        const int m = m0 + wm * 32 + lane;
        const size_t base = (size_t)(m >> 16) * C_SZ * 65536 + (m & 65535);
        #pragma unroll 8
        for (int cc = 0; cc < 32; cc++) {
            int nn = n0 + wn * 32 + cc;
            ((float*)outp)[base + (size_t)nn * 65536] = Ep[lane * 36 + cc];
        }
    }
}

// -------- window attention (wmma): one block per (window, head), 128 threads
__global__ __launch_bounds__(128) void attn_kernel() {
    __shared__ __align__(16) __nv_bfloat16 qs[64 * 32];
    __shared__ __align__(16) __nv_bfloat16 ks[64 * 32];
    __shared__ __align__(16) __nv_bfloat16 vs[64 * 32];
    __shared__ __align__(16) float         Sf[64 * 68];
    __shared__ __align__(16) __nv_bfloat16 Pm[64 * 64];
    __shared__ __align__(16) float         Os[4 * 16 * 36];

    const int win  = blockIdx.x;
    const int head = blockIdx.y;
    const int tid  = threadIdx.x;
    const int warp = tid >> 5, lane = tid & 31;
    const float scale = 0.17677669529663687f;

    const int b  = win >> 10;
    const int wh = (win >> 5) & 31;
    const int ww = win & 31;
    const int pixbase = b * 65536 + (wh * 8) * 256 + ww * 8;

    // gather q,k,v for this (window, head): 64 tokens x 32 ch (uint4 = 8 bf16)
    #pragma unroll
    for (int it = 0; it < 2; it++) {
        int u = tid + it * 128;          // 0..255
        int t = u >> 2, seg = u & 3;
        int pix = pixbase + (t >> 3) * 256 + (t & 7);
        const uint4* rp = (const uint4*)(g_qkv + (size_t)pix * (3 * C_SZ) + head * 32);
        ((uint4*)qs)[t * 4 + seg] = rp[seg];
        ((uint4*)ks)[t * 4 + seg] = rp[seg + 24];   // +192 ch = 24 uint4
        ((uint4*)vs)[t * 4 + seg] = rp[seg + 48];   // +384 ch
    }
    __syncthreads();

    // S = q @ k^T  (warp wm owns rows [16wm, 16wm+16))
    {
        wmma::fragment<wmma::accumulator, 16, 16, 16, float> acc[4];
        #pragma unroll
        for (int j = 0; j < 4; j++) wmma::fill_fragment(acc[j], 0.f);
        #pragma unroll
        for (int kk = 0; kk < 2; kk++) {
            wmma::fragment<wmma::matrix_a, 16, 16, 16, __nv_bfloat16, wmma::row_major> fa;
            wmma::load_matrix_sync(fa, qs + (warp * 16) * 32 + kk * 16, 32);
            #pragma unroll
            for (int j = 0; j < 4; j++) {
                wmma::fragment<wmma::matrix_b, 16, 16, 16, __nv_bfloat16, wmma::col_major> fb;
                wmma::load_matrix_sync(fb, ks + (j * 16) * 32 + kk * 16, 32);
                wmma::mma_sync(acc[j], fa, fb, acc[j]);
            }
        }
        #pragma unroll
        for (int j = 0; j < 4; j++)
            wmma::store_matrix_sync(Sf + (warp * 16) * 68 + j * 16, acc[j], 68, wmma::mem_row_major);
    }
    __syncwarp();

    // softmax over rows (2 threads per row, warp-private rows)
    {
        int row = tid >> 1, h = tid & 1;
        float* Sr = Sf + row * 68 + h * 32;
        float mx = -1e30f;
        #pragma unroll 8
        for (int c = 0; c < 32; c++) mx = fmaxf(mx, Sr[c]);
        mx = fmaxf(mx, __shfl_xor_sync(0xffffffffu, mx, 1));
        float sum = 0.f;
        #pragma unroll 8
        for (int c = 0; c < 32; c++) {
            float e = __expf((Sr[c] - mx) * scale);
            Sr[c] = e; sum += e;
        }
        sum += __shfl_xor_sync(0xffffffffu, sum, 1);
        float inv = 1.f / sum;
        #pragma unroll 8
        for (int c = 0; c < 32; c++)
            Pm[row * 64 + h * 32 + c] = __float2bfloat16(Sr[c] * inv);
    }
    __syncwarp();

    // out = P @ V  (warp wm owns rows [16wm, +16))
    {
        wmma::fragment<wmma::accumulator, 16, 16, 16, float> o0, o1;
        wmma::fill_fragment(o0, 0.f); wmma::fill_fragment(o1, 0.f);
        #pragma unroll
        for (int kk = 0; kk < 4; kk++) {
            wmma::fragment<wmma::matrix_a, 16, 16, 16, __nv_bfloat16, wmma::row_major> fa;
            wmma::load_matrix_sync(fa, Pm + (warp * 16) * 64 + kk * 16, 64);
            wmma::fragment<wmma::matrix_b, 16, 16, 16, __nv_bfloat16, wmma::row_major> fb0, fb1;
            wmma::load_matrix_sync(fb0, vs + (kk * 16) * 32, 32);
            wmma::load_matrix_sync(fb1, vs + (kk * 16) * 32 + 16, 32);
            wmma::mma_sync(o0, fa, fb0, o0);
            wmma::mma_sync(o1, fa, fb1, o1);
        }
        float* So = Os + warp * (16 * 36);
        wmma::store_matrix_sync(So,      o0, 36, wmma::mem_row_major);
        wmma::store_matrix_sync(So + 16, o1, 36, wmma::mem_row_major);
        __syncwarp();
        #pragma unroll
        for (int r = 0; r < 16; r++) {
            int t = warp * 16 + r;
            int pix = pixbase + (t >> 3) * 256 + (t & 7);
            g_attn[(size_t)pix * C_SZ + head * 32 + lane] = __float2bfloat16(So[r * 36 + lane]);
        }
    }
}

// -------- LN2: warp per token over fp32 y1 --------
__global__ __launch_bounds__(256) void ln2_kernel(const float* __restrict__ w,
                                                  const float* __restrict__ b) {
    int t    = blockIdx.x * 8 + (threadIdx.x >> 5);
    int lane = threadIdx.x & 31;
    const float* row = g_y1 + (size_t)t * C_SZ;
    float v[6];
    float sum = 0.f;
    #pragma unroll
    for (int i = 0; i < 6; i++) { v[i] = row[lane + i * 32]; sum += v[i]; }
    #pragma unroll
    for (int o = 16; o; o >>= 1) sum += __shfl_xor_sync(0xffffffffu, sum, o);
    float mu = sum * (1.f / C_SZ);
    float sq = 0.f;
    #pragma unroll
    for (int i = 0; i < 6; i++) { float d = v[i] - mu; sq += d * d; }
    #pragma unroll
    for (int o = 16; o; o >>= 1) sq += __shfl_xor_sync(0xffffffffu, sq, o);
    float rs = rsqrtf(sq * (1.f / C_SZ) + 1e-5f);
    __nv_bfloat16* out = g_hln + (size_t)t * C_SZ;
    #pragma unroll
    for (int i = 0; i < 6; i++) {
        int c = lane + i * 32;
        out[c] = __float2bfloat16((v[i] - mu) * rs * w[c] + b[c]);
    }
}

extern "C" void kernel_launch(void* const* d_in, const int* in_sizes, int n_in,
                              void* d_out, int out_size) {
    const float* x     = (const float*)d_in[0];
    const float* n1w   = (const float*)d_in[1];
    const float* n1b   = (const float*)d_in[2];
    const float* qkvw  = (const float*)d_in[3];
    const float* qkvb  = (const float*)d_in[4];
    const float* projw = (const float*)d_in[5];
    const float* projb = (const float*)d_in[6];
    const float* n2w   = (const float*)d_in[7];
    const float* n2b   = (const float*)d_in[8];
    const float* w1    = (const float*)d_in[9];
    const float* b1    = (const float*)d_in[10];
    const float* w2    = (const float*)d_in[11];
    const float* b2    = (const float*)d_in[12];
    float* out = (float*)d_out;

    void *p_xln, *p_qkv, *p_attn, *p_y1, *p_hln, *p_hid, *p_wq, *p_wp, *p_w1, *p_w2, *p_xres;
    cudaGetSymbolAddress(&p_xln, g_xln);
    cudaGetSymbolAddress(&p_xres, g_xres);
    cudaGetSymbolAddress(&p_qkv, g_qkv);
    cudaGetSymbolAddress(&p_attn, g_attn);
    cudaGetSymbolAddress(&p_y1, g_y1);
    cudaGetSymbolAddress(&p_hln, g_hln);
    cudaGetSymbolAddress(&p_hid, g_hid);
    cudaGetSymbolAddress(&p_wq, g_wq);
    cudaGetSymbolAddress(&p_wp, g_wp);
    cudaGetSymbolAddress(&p_w1, g_w1);
    cudaGetSymbolAddress(&p_w2, g_w2);

    cvt_kernel<<<(3*C_SZ*C_SZ + 255)/256, 256>>>(qkvw, (__nv_bfloat16*)p_wq, 3*C_SZ*C_SZ);
    cvt_kernel<<<(C_SZ*C_SZ + 255)/256, 256>>>(projw, (__nv_bfloat16*)p_wp, C_SZ*C_SZ);
    cvt_kernel<<<(HID_SZ*C_SZ + 255)/256, 256>>>(w1, (__nv_bfloat16*)p_w1, HID_SZ*C_SZ);
    cvt_kernel<<<(C_SZ*HID_SZ + 255)/256, 256>>>(w2, (__nv_bfloat16*)p_w2, C_SZ*HID_SZ);

    // 1) LN1 (single pass) + token-major fp32 residual copy
    ln1_kernel<<<TOK/32, 256>>>(x, n1w, n1b);

    // 2) QKV GEMM: [TOK,192] x [576,192]^T
    gemm128<0><<<dim3(9, TOK/128), 256>>>((const __nv_bfloat16*)p_xln,
                                          (const __nv_bfloat16*)p_wq,
                                          qkvb, C_SZ, 3*C_SZ, p_qkv, nullptr);

    // 3) window attention (tensor cores)
    attn_kernel<<<dim3(NWIN, NH_SZ), 128>>>();

    // 4) proj + residual -> fp32 y1 (token-major)
    gemm128<2><<<dim3(3, TOK/128), 256>>>((const __nv_bfloat16*)p_attn,
                                          (const __nv_bfloat16*)p_wp,
                                          projb, C_SZ, C_SZ, p_y1, (const float*)p_xres);

    // 5) LN2
    ln2_kernel<<<TOK/8, 256>>>(n2w, n2b);

    // 6) MLP1 + GELU
    gemm128<1><<<dim3(12, TOK/128), 256>>>((const __nv_bfloat16*)p_hln,
                                           (const __nv_bfloat16*)p_w1,
                                           b1, C_SZ, HID_SZ, p_hid, nullptr);

    // 7) MLP2 + residual -> BCHW output (coalesced)
    gemm128<3><<<dim3(3, TOK/128), 256>>>((const __nv_bfloat16*)p_hid,
                                          (const __nv_bfloat16*)p_w2,
                                          b2, HID_SZ, C_SZ, out, (const float*)p_y1);
}

// round 3
// speedup vs baseline: 1.8511x; 1.0185x over previous
#include <cuda_runtime.h>
#include <cuda_bf16.h>
#include <mma.h>

using namespace nvcuda;

#define C_SZ   192
#define TOK    262144
#define NWIN   4096
#define HID_SZ 768

// -------- scratch (device globals) --------
__device__ float         g_y1 [(size_t)TOK * C_SZ];
__device__ __nv_bfloat16 g_hln[(size_t)TOK * C_SZ];
__device__ __nv_bfloat16 g_hid[(size_t)TOK * HID_SZ];
__device__ __nv_bfloat16 g_wq [3 * C_SZ * C_SZ];
__device__ __nv_bfloat16 g_wp [C_SZ * C_SZ];
__device__ __nv_bfloat16 g_w1 [HID_SZ * C_SZ];
__device__ __nv_bfloat16 g_w2 [C_SZ * HID_SZ];

// -------- helpers --------
__device__ __forceinline__ unsigned smem_u32(const void* p) {
    return (unsigned)__cvta_generic_to_shared(p);
}
__device__ __forceinline__ void cp16(void* s, const void* g) {
    asm volatile("cp.async.cg.shared.global [%0], [%1], 16;\n"
                 :: "r"(smem_u32(s)), "l"(g));
}
#define CP_COMMIT asm volatile("cp.async.commit_group;\n" ::: "memory")
#define CP_WAIT(N) asm volatile("cp.async.wait_group %0;\n" :: "n"(N) : "memory")

__global__ void cvt_kernel(const float* __restrict__ in, __nv_bfloat16* __restrict__ out, int n) {
    int i = blockIdx.x * blockDim.x + threadIdx.x;
    if (i < n) out[i] = __float2bfloat16(in[i]);
}

// ===================== megakernel: LN1 + QKV + attention + proj + residual + LN2 ==========
// one block = one 8x8 window (64 tokens), 256 threads
// smem layout (bytes):
//   XL   @ 0       : 64x200 bf16 (25,600)   xln, later attn_out
//   R2   @ 25600   : union{ XS 192x68 f32 (52,224) | QKV 64x584 bf16 (74,752) | PO 64x200 f32 (51,200) }
//   R3   @ 100352  : union{ qkvBst 2x288x16 bf16 (18,432) + scratch 8x256 f32 (8,192)
//                           | Sf 2x64x68 f32 (34,816) + Pm 2x64x64 bf16 (16,384)
//                           | projBst 2x192x16 bf16 (12,288) }
//   BIAS @ 151552  : SB 576f + PB 192f + MU 64f + RS 64f
#define XL_OFF   0
#define R2_OFF   25600
#define R3_OFF   100352
#define BIAS_OFF 151552
#define SMEM_TOT 155648

__global__ __launch_bounds__(256) void mega_kernel(const float* __restrict__ x,
                                                   const float* __restrict__ n1w,
                                                   const float* __restrict__ n1b,
                                                   const float* __restrict__ qkvb,
                                                   const float* __restrict__ projb,
                                                   const float* __restrict__ n2w,
                                                   const float* __restrict__ n2b) {
    extern __shared__ unsigned char smem[];
    __nv_bfloat16* XL = (__nv_bfloat16*)(smem + XL_OFF);
    float*         XS = (float*)(smem + R2_OFF);
    __nv_bfloat16* QK = (__nv_bfloat16*)(smem + R2_OFF);
    float*         PO = (float*)(smem + R2_OFF);
    float* SB = (float*)(smem + BIAS_OFF);
    float* PB = SB + 576;
    float* MU = PB + 192;
    float* RS = MU + 64;

    const int tid  = threadIdx.x;
    const int warp = tid >> 5, lane = tid & 31;
    const int win = blockIdx.x;
    const int b  = win >> 10;
    const int wh = (win >> 5) & 31;
    const int ww = win & 31;
    const int pixbase = b * 65536 + (wh * 8) * 256 + ww * 8;
    const float* xb = x + (size_t)b * C_SZ * 65536 + (wh * 8) * 256 + ww * 8;

    // ---- phase -1: biases to smem + x window tile (channel-major) via cp.async ----
    for (int u = tid; u < 576; u += 256) SB[u] = qkvb[u];
    if (tid < 192) PB[tid] = projb[tid];
    #pragma unroll
    for (int i = 0; i < 12; i++) {
        int u = tid + i * 256;           // 0..3071 = 192ch * 8row * 2half
        int pair = u >> 1, hf = u & 1;
        int c = pair >> 3, hr = pair & 7;
        cp16(smem + R2_OFF + ((c * 68 + hr * 8 + hf * 4) << 2),
             xb + (size_t)c * 65536 + hr * 256 + hf * 4);
    }
    CP_COMMIT; CP_WAIT(0);
    __syncthreads();

    // ---- phase 0: LN1 over channels, write XL bf16 [64][200] ----
    {
        int p = tid >> 2, q = tid & 3;
        float s = 0.f, sq = 0.f;
        #pragma unroll
        for (int j = 0; j < 48; j++) {
            float v = XS[(q + 4 * j) * 68 + p];
            s += v; sq += v * v;
        }
        s  += __shfl_xor_sync(0xffffffffu, s, 1);
        sq += __shfl_xor_sync(0xffffffffu, sq, 1);
        s  += __shfl_xor_sync(0xffffffffu, s, 2);
        sq += __shfl_xor_sync(0xffffffffu, sq, 2);
        float mu = s * (1.f / 192.f);
        float rs = rsqrtf(sq * (1.f / 192.f) - mu * mu + 1e-5f);
        #pragma unroll
        for (int j = 0; j < 48; j++) {
            int c = q + 4 * j;
            float v = XS[c * 68 + p];
            XL[p * 200 + c] = __float2bfloat16((v - mu) * rs * n1w[c] + n1b[c]);
        }
    }
    __syncthreads();

    const int ms = warp & 3;      // m-strip (16 rows)
    const int nh = warp >> 2;     // n-half

    // ---- phase 1: QKV = XL @ Wq^T + b : [64][576] bf16, two N-halves of 288 ----
    {
        __nv_bfloat16* Bst = (__nv_bfloat16*)(smem + R3_OFF);         // 2 x 288x16
        float* scratch = (float*)(smem + R3_OFF + 18432) + warp * 256; // 16x16 per warp

        for (int half = 0; half < 2; half++) {
            wmma::fragment<wmma::accumulator, 16, 16, 16, float> acc[9];
            #pragma unroll
            for (int t = 0; t < 9; t++) wmma::fill_fragment(acc[t], 0.f);

            // stage k-slice of 288 weight rows
            auto stageq = [&](int st, int k0) {
                #pragma unroll
                for (int i = 0; i < 3; i++) {
                    int u = tid + i * 256;
                    if (u < 576) {
                        int rl = u >> 1, hf = u & 1;
                        cp16((unsigned char*)Bst + st * 9216 + rl * 32 + hf * 16,
                             g_wq + (size_t)(half * 288 + rl) * 192 + k0 + hf * 8);
                    }
                }
            };
            stageq(0, 0); CP_COMMIT;
            for (int ks = 0; ks < 12; ks++) {
                if (ks < 11) { stageq((ks + 1) & 1, (ks + 1) * 16); CP_COMMIT; CP_WAIT(1); }
                else         { CP_WAIT(0); }
                __syncthreads();
                const __nv_bfloat16* bb = Bst + (ks & 1) * 4608;
                wmma::fragment<wmma::matrix_a, 16, 16, 16, __nv_bfloat16, wmma::row_major> fa;
                wmma::load_matrix_sync(fa, XL + (ms * 16) * 200 + ks * 16, 200);
                #pragma unroll
                for (int t = 0; t < 9; t++) {
                    wmma::fragment<wmma::matrix_b, 16, 16, 16, __nv_bfloat16, wmma::col_major> fb;
                    wmma::load_matrix_sync(fb, bb + (nh * 144 + t * 16) * 16, 16);
                    wmma::mma_sync(acc[t], fa, fb, acc[t]);
                }
                __syncthreads();
            }
            // epilogue: +bias, convert to bf16 into QK
            #pragma unroll
            for (int t = 0; t < 9; t++) {
                wmma::store_matrix_sync(scratch, acc[t], 16, wmma::mem_row_major);
                __syncwarp();
                int n0 = half * 288 + nh * 144 + t * 16;
                #pragma unroll
                for (int e = 0; e < 8; e++) {
                    int idx = lane + e * 32;
                    int r = idx >> 4, cc = idx & 15;
                    QK[(ms * 16 + r) * 584 + n0 + cc] =
                        __float2bfloat16(scratch[r * 16 + cc] + SB[n0 + cc]);
                }
                __syncwarp();
            }
        }
    }
    __syncthreads();

    // ---- phase 2: attention, 2 heads per iteration (warps 0-3 / 4-7) ----
    for (int p2 = 0; p2 < 3; p2++) {
        const int side = warp >> 2, wr = warp & 3;
        const int h = p2 * 2 + side;
        float* Sf = (float*)(smem + R3_OFF) + side * 4352;            // 64x68
        __nv_bfloat16* Pm = (__nv_bfloat16*)(smem + R3_OFF + 34816) + side * 4096; // 64x64

        // S = q @ k^T
        {
            wmma::fragment<wmma::accumulator, 16, 16, 16, float> s4[4];
            #pragma unroll
            for (int t = 0; t < 4; t++) wmma::fill_fragment(s4[t], 0.f);
            #pragma unroll
            for (int kk = 0; kk < 2; kk++) {
                wmma::fragment<wmma::matrix_a, 16, 16, 16, __nv_bfloat16, wmma::row_major> fq;
                wmma::load_matrix_sync(fq, QK + (wr * 16) * 584 + h * 32 + kk * 16, 584);
                #pragma unroll
                for (int mt = 0; mt < 4; mt++) {
                    wmma::fragment<wmma::matrix_b, 16, 16, 16, __nv_bfloat16, wmma::col_major> fk;
                    wmma::load_matrix_sync(fk, QK + (mt * 16) * 584 + 192 + h * 32 + kk * 16, 584);
                    wmma::mma_sync(s4[mt], fq, fk, s4[mt]);
                }
            }
            #pragma unroll
            for (int mt = 0; mt < 4; mt++)
                wmma::store_matrix_sync(Sf + (wr * 16) * 68 + mt * 16, s4[mt], 68, wmma::mem_row_major);
        }
        __syncthreads();

        // softmax (scale folded into exp)
        {
            int st = tid >> 7;
            float* Sft = (float*)(smem + R3_OFF) + st * 4352;
            __nv_bfloat16* Pt = (__nv_bfloat16*)(smem + R3_OFF + 34816) + st * 4096;
            int row = (tid & 127) >> 1, hf = tid & 1;
            float* Sr = Sft + row * 68 + hf * 32;
            float mx = -1e30f;
            #pragma unroll
            for (int c = 0; c < 32; c++) mx = fmaxf(mx, Sr[c]);
            mx = fmaxf(mx, __shfl_xor_sync(0xffffffffu, mx, 1));
            float ev[32], sum = 0.f;
            #pragma unroll
            for (int c = 0; c < 32; c++) {
                ev[c] = __expf((Sr[c] - mx) * 0.17677669529663687f);
                sum += ev[c];
            }
            sum += __shfl_xor_sync(0xffffffffu, sum, 1);
            float inv = 1.f / sum;
            #pragma unroll
            for (int c = 0; c < 32; c++)
                Pt[row * 64 + hf * 32 + c] = __float2bfloat16(ev[c] * inv);
        }
        __syncthreads();

        // O = P @ V -> attn_out (XL region, bf16 cols h*32..)
        {
            wmma::fragment<wmma::accumulator, 16, 16, 16, float> o0, o1;
            wmma::fill_fragment(o0, 0.f); wmma::fill_fragment(o1, 0.f);
            #pragma unroll
            for (int kk = 0; kk < 4; kk++) {
                wmma::fragment<wmma::matrix_a, 16, 16, 16, __nv_bfloat16, wmma::row_major> fp;
                wmma::load_matrix_sync(fp, Pm + (wr * 16) * 64 + kk * 16, 64);
                wmma::fragment<wmma::matrix_b, 16, 16, 16, __nv_bfloat16, wmma::row_major> fv0, fv1;
                wmma::load_matrix_sync(fv0, QK + (kk * 16) * 584 + 384 + h * 32, 584);
                wmma::load_matrix_sync(fv1, QK + (kk * 16) * 584 + 384 + h * 32 + 16, 584);
                wmma::mma_sync(o0, fp, fv0, o0);
                wmma::mma_sync(o1, fp, fv1, o1);
            }
            float* stg = (float*)(smem + R3_OFF) + side * 4352 + wr * 512;  // 16x32
            wmma::store_matrix_sync(stg,      o0, 32, wmma::mem_row_major);
            wmma::store_matrix_sync(stg + 16, o1, 32, wmma::mem_row_major);
            __syncwarp();
            #pragma unroll
            for (int e = 0; e < 16; e++) {
                int idx = lane + e * 32;
                int r = idx >> 5, cc = idx & 31;
                XL[(wr * 16 + r) * 200 + h * 32 + cc] = __float2bfloat16(stg[r * 32 + cc]);
            }
        }
        __syncthreads();
    }

    // ---- phase 3: proj = attn_out @ Wp^T -> PO fp32 [64][200] ----
    {
        __nv_bfloat16* BstP = (__nv_bfloat16*)(smem + R3_OFF);    // 2 x 192x16
        wmma::fragment<wmma::accumulator, 16, 16, 16, float> pa[6];
        #pragma unroll
        for (int t = 0; t < 6; t++) wmma::fill_fragment(pa[t], 0.f);

        auto stagep = [&](int st, int k0) {
            #pragma unroll
            for (int i = 0; i < 2; i++) {
                int u = tid + i * 256;
                if (u < 384) {
                    int rl = u >> 1, hf = u & 1;
                    cp16((unsigned char*)BstP + st * 6144 + rl * 32 + hf * 16,
                         g_wp + (size_t)rl * 192 + k0 + hf * 8);
                }
            }
        };
        stagep(0, 0); CP_COMMIT;
        for (int ks = 0; ks < 12; ks++) {
            if (ks < 11) { stagep((ks + 1) & 1, (ks + 1) * 16); CP_COMMIT; CP_WAIT(1); }
            else         { CP_WAIT(0); }
            __syncthreads();
            const __nv_bfloat16* bb = BstP + (ks & 1) * 3072;
            wmma::fragment<wmma::matrix_a, 16, 16, 16, __nv_bfloat16, wmma::row_major> fa;
            wmma::load_matrix_sync(fa, XL + (ms * 16) * 200 + ks * 16, 200);
            #pragma unroll
            for (int t = 0; t < 6; t++) {
                wmma::fragment<wmma::matrix_b, 16, 16, 16, __nv_bfloat16, wmma::col_major> fb;
                wmma::load_matrix_sync(fb, bb + (nh * 96 + t * 16) * 16, 16);
                wmma::mma_sync(pa[t], fa, fb, pa[t]);
            }
            __syncthreads();
        }
        #pragma unroll
        for (int t = 0; t < 6; t++)
            wmma::store_matrix_sync(PO + (ms * 16) * 200 + nh * 96 + t * 16, pa[t], 200, wmma::mem_row_major);
    }
    __syncthreads();

    // ---- phase 4: residual (x from L2) + bias, LN2, write y1 + hln ----
    #pragma unroll
    for (int i = 0; i < 48; i++) {
        int e = i * 256 + tid;          // 0..12287 : c = e>>6, p = e&63
        int c = e >> 6, p = e & 63;
        float xv = xb[(size_t)c * 65536 + (p >> 3) * 256 + (p & 7)];
        PO[p * 200 + c] += xv + PB[c];
    }
    __syncthreads();
    {
        int p = tid >> 2, q = tid & 3;
        float s = 0.f, sq = 0.f;
        #pragma unroll
        for (int j = 0; j < 48; j++) {
            float v = PO[p * 200 + q * 48 + j];
            s += v; sq += v * v;
        }
        s  += __shfl_xor_sync(0xffffffffu, s, 1);
        sq += __shfl_xor_sync(0xffffffffu, sq, 1);
        s  += __shfl_xor_sync(0xffffffffu, s, 2);
        sq += __shfl_xor_sync(0xffffffffu, sq, 2);
        if (q == 0) {
            float mu = s * (1.f / 192.f);
            MU[p] = mu;
            RS[p] = rsqrtf(sq * (1.f / 192.f) - mu * mu + 1e-5f);
        }
    }
    __syncthreads();
    #pragma unroll
    for (int i = 0; i < 48; i++) {
        int e = i * 256 + tid;
        int p = e / 192, c = e - p * 192;
        int pix = pixbase + (p >> 3) * 256 + (p & 7);
        float v = PO[p * 200 + c];
        g_y1[(size_t)pix * 192 + c] = v;
        g_hln[(size_t)pix * 192 + c] = __float2bfloat16((v - MU[p]) * RS[p] * n2w[c] + n2b[c]);
    }
}

// ===================== pipelined 128x64 GEMM for MLP =====================
// MODE 1: GELU -> bf16 out [M,N]
// MODE 3: outBCHW[b,n,h,w] = res[m*192+n] + v
template<int MODE>
__global__ __launch_bounds__(256) void gemm128(const __nv_bfloat16* __restrict__ A,
                                               const __nv_bfloat16* __restrict__ W,
                                               const float* __restrict__ bias,
                                               int K, int N,
                                               void* __restrict__ outp,
                                               const float* __restrict__ res) {
    __shared__ __align__(16) unsigned char sbuf[36864];
    const int m0 = blockIdx.y * 128;
    const int n0 = blockIdx.x * 64;
    const int tid = threadIdx.x;
    const int warp = tid >> 5, lane = tid & 31;
    const int wm = warp >> 1, wn = warp & 1;

    wmma::fragment<wmma::accumulator, 16, 16, 16, float> a00, a01, a10, a11;
    wmma::fill_fragment(a00, 0.f); wmma::fill_fragment(a01, 0.f);
    wmma::fill_fragment(a10, 0.f); wmma::fill_fragment(a11, 0.f);

    auto load_stage = [&](int st, int kk) {
        __nv_bfloat16* as = (__nv_bfloat16*)(sbuf + st * 12288);
        __nv_bfloat16* bs = as + 128 * 32;
        #pragma unroll
        for (int it = 0; it < 2; it++) {
            int u = tid + it * 256;
            int row = u >> 2, q = u & 3;
            cp16(as + row * 32 + q * 8, A + (size_t)(m0 + row) * K + kk + q * 8);
        }
        { int row = tid >> 2, q = tid & 3;
          cp16(bs + row * 32 + q * 8, W + (size_t)(n0 + row) * K + kk + q * 8); }
    };

    const int nst = K >> 5;
    load_stage(0, 0); CP_COMMIT;
    for (int s = 0; s < nst; s++) {
        if (s + 1 < nst) { load_stage((s + 1) & 1, (s + 1) * 32); CP_COMMIT; CP_WAIT(1); }
        else             { CP_WAIT(0); }
        __syncthreads();
        const __nv_bfloat16* as = (const __nv_bfloat16*)(sbuf + (s & 1) * 12288);
        const __nv_bfloat16* bs = as + 128 * 32;
        #pragma unroll
        for (int ks = 0; ks < 2; ks++) {
            wmma::fragment<wmma::matrix_a, 16, 16, 16, __nv_bfloat16, wmma::row_major> fa0, fa1;
            wmma::fragment<wmma::matrix_b, 16, 16, 16, __nv_bfloat16, wmma::col_major> fb0, fb1;
            wmma::load_matrix_sync(fa0, as + (wm * 32) * 32 + ks * 16, 32);
            wmma::load_matrix_sync(fa1, as + (wm * 32 + 16) * 32 + ks * 16, 32);
            wmma::load_matrix_sync(fb0, bs + (wn * 32) * 32 + ks * 16, 32);
            wmma::load_matrix_sync(fb1, bs + (wn * 32 + 16) * 32 + ks * 16, 32);
            wmma::mma_sync(a00, fa0, fb0, a00);
            wmma::mma_sync(a01, fa0, fb1, a01);
            wmma::mma_sync(a10, fa1, fb0, a10);
            wmma::mma_sync(a11, fa1, fb1, a11);
        }
        __syncthreads();
    }

    float* Ep = (float*)sbuf + warp * (32 * 36);
    wmma::store_matrix_sync(Ep,                a00, 36, wmma::mem_row_major);
    wmma::store_matrix_sync(Ep + 16,           a01, 36, wmma::mem_row_major);
    wmma::store_matrix_sync(Ep + 16 * 36,      a10, 36, wmma::mem_row_major);
    wmma::store_matrix_sync(Ep + 16 * 36 + 16, a11, 36, wmma::mem_row_major);
    __syncwarp();

    const int n = n0 + wn * 32 + lane;
    const float bn = bias[n];

    if (MODE == 1) {
        #pragma unroll 4
        for (int r = 0; r < 32; r++) {
            float v = Ep[r * 36 + lane] + bn;
            v = 0.5f * v * (1.f + erff(v * 0.70710678118654752f));
            ((__nv_bfloat16*)outp)[(size_t)(m0 + wm * 32 + r) * N + n] = __float2bfloat16(v);
        }
    } else { // MODE 3
        #pragma unroll 8
        for (int r = 0; r < 32; r++) {
            size_t off = (size_t)(m0 + wm * 32 + r) * C_SZ + n;
            Ep[r * 36 + lane] += bn + res[off];
        }
        __syncwarp();
        const int m = m0 + wm * 32 + lane;
        const size_t base = (size_t)(m >> 16) * C_SZ * 65536 + (m & 65535);
        #pragma unroll 8
        for (int cc = 0; cc < 32; cc++) {
            int nn = n0 + wn * 32 + cc;
            ((float*)outp)[base + (size_t)nn * 65536] = Ep[lane * 36 + cc];
        }
    }
}

extern "C" void kernel_launch(void* const* d_in, const int* in_sizes, int n_in,
                              void* d_out, int out_size) {
    const float* x     = (const float*)d_in[0];
    const float* n1w   = (const float*)d_in[1];
    const float* n1b   = (const float*)d_in[2];
    const float* qkvw  = (const float*)d_in[3];
    const float* qkvb  = (const float*)d_in[4];
    const float* projw = (const float*)d_in[5];
    const float* projb = (const float*)d_in[6];
    const float* n2w   = (const float*)d_in[7];
    const float* n2b   = (const float*)d_in[8];
    const float* w1    = (const float*)d_in[9];
    const float* b1    = (const float*)d_in[10];
    const float* w2    = (const float*)d_in[11];
    const float* b2    = (const float*)d_in[12];
    float* out = (float*)d_out;

    void *p_y1, *p_hln, *p_hid, *p_wq, *p_wp, *p_w1, *p_w2;
    cudaGetSymbolAddress(&p_y1, g_y1);
    cudaGetSymbolAddress(&p_hln, g_hln);
    cudaGetSymbolAddress(&p_hid, g_hid);
    cudaGetSymbolAddress(&p_wq, g_wq);
    cudaGetSymbolAddress(&p_wp, g_wp);
    cudaGetSymbolAddress(&p_w1, g_w1);
    cudaGetSymbolAddress(&p_w2, g_w2);

    cudaFuncSetAttribute(mega_kernel, cudaFuncAttributeMaxDynamicSharedMemorySize, SMEM_TOT);

    cvt_kernel<<<(3*C_SZ*C_SZ + 255)/256, 256>>>(qkvw, (__nv_bfloat16*)p_wq, 3*C_SZ*C_SZ);
    cvt_kernel<<<(C_SZ*C_SZ + 255)/256, 256>>>(projw, (__nv_bfloat16*)p_wp, C_SZ*C_SZ);
    cvt_kernel<<<(HID_SZ*C_SZ + 255)/256, 256>>>(w1, (__nv_bfloat16*)p_w1, HID_SZ*C_SZ);
    cvt_kernel<<<(C_SZ*HID_SZ + 255)/256, 256>>>(w2, (__nv_bfloat16*)p_w2, C_SZ*HID_SZ);

    // fused LN1 + QKV + attention + proj + residual + LN2
    mega_kernel<<<NWIN, 256, SMEM_TOT>>>(x, n1w, n1b, qkvb, projb, n2w, n2b);

    // MLP1 + GELU
    gemm128<1><<<dim3(12, TOK/128), 256>>>((const __nv_bfloat16*)p_hln,
                                           (const __nv_bfloat16*)p_w1,
                                           b1, C_SZ, HID_SZ, p_hid, nullptr);

    // MLP2 + residual -> BCHW output
    gemm128<3><<<dim3(3, TOK/128), 256>>>((const __nv_bfloat16*)p_hid,
                                          (const __nv_bfloat16*)p_w2,
                                          b2, HID_SZ, C_SZ, out, (const float*)p_y1);
}

// round 4
// speedup vs baseline: 2.2769x; 1.2300x over previous
#include <cuda_runtime.h>
#include <cuda_bf16.h>
#include <mma.h>

using namespace nvcuda;

#define C_SZ   192
#define TOK    262144
#define NWIN   4096
#define HID_SZ 768

// -------- scratch (device globals) --------
__device__ __nv_bfloat16 g_xln [(size_t)TOK * C_SZ];
__device__ float         g_xres[(size_t)TOK * C_SZ];
__device__ __nv_bfloat16 g_qkv [(size_t)TOK * 3 * C_SZ];
__device__ float         g_y1  [(size_t)TOK * C_SZ];
__device__ __nv_bfloat16 g_hln [(size_t)TOK * C_SZ];
__device__ __nv_bfloat16 g_hid [(size_t)TOK * HID_SZ];
__device__ __nv_bfloat16 g_wq  [3 * C_SZ * C_SZ];
__device__ __nv_bfloat16 g_wp  [C_SZ * C_SZ];
__device__ __nv_bfloat16 g_w1  [HID_SZ * C_SZ];
__device__ __nv_bfloat16 g_w2  [C_SZ * HID_SZ];

// -------- helpers --------
__device__ __forceinline__ unsigned smem_u32(const void* p) {
    return (unsigned)__cvta_generic_to_shared(p);
}
__device__ __forceinline__ void cp16(void* s, const void* g) {
    asm volatile("cp.async.cg.shared.global [%0], [%1], 16;\n"
                 :: "r"(smem_u32(s)), "l"(g));
}
#define CP_COMMIT asm volatile("cp.async.commit_group;\n" ::: "memory")
#define CP_WAIT(N) asm volatile("cp.async.wait_group %0;\n" :: "n"(N) : "memory")

// -------- fused weight convert --------
__global__ void cvt_all(const float* __restrict__ a, const float* __restrict__ b,
                        const float* __restrict__ c, const float* __restrict__ d) {
    int i = blockIdx.x * 256 + threadIdx.x;
    if (i < 110592)       g_wq[i]          = __float2bfloat16(a[i]);
    else if (i < 147456)  g_wp[i - 110592] = __float2bfloat16(b[i - 110592]);
    else if (i < 294912)  g_w1[i - 147456] = __float2bfloat16(c[i - 147456]);
    else if (i < 442368)  g_w2[i - 294912] = __float2bfloat16(d[i - 294912]);
}

// -------- LN1: single pass over x (BCHW) -> token-major g_xln (bf16) + g_xres (fp32)
__global__ __launch_bounds__(256) void ln1_kernel(const float* __restrict__ x,
                                                  const float* __restrict__ w,
                                                  const float* __restrict__ b) {
    __shared__ float xs[32 * 193];
    __shared__ float smu[32], srs[32];
    const int tid = threadIdx.x;
    const int pix0 = blockIdx.x * 32;
    const int bidx = pix0 >> 16;
    const int hw0  = pix0 & 65535;
    const float* xb = x + (size_t)bidx * C_SZ * 65536 + hw0;

    #pragma unroll 6
    for (int i = tid; i < 32 * 192; i += 256) {
        int c = i >> 5, p = i & 31;
        xs[p * 193 + c] = xb[(size_t)c * 65536 + p];
    }
    __syncthreads();

    if (tid < 64) {
        int t = tid >> 1, h = tid & 1;
        const float* row = xs + t * 193 + h * 96;
        float s = 0.f, sq = 0.f;
        #pragma unroll 8
        for (int j = 0; j < 96; j++) { float v = row[j]; s += v; sq += v * v; }
        s  += __shfl_xor_sync(0xffffffffu, s, 1);
        sq += __shfl_xor_sync(0xffffffffu, sq, 1);
        if (h == 0) {
            float mu = s * (1.f / C_SZ);
            smu[t] = mu;
            srs[t] = rsqrtf(sq * (1.f / C_SZ) - mu * mu + 1e-5f);
        }
    }
    __syncthreads();

    #pragma unroll 6
    for (int i = tid; i < 32 * 192; i += 256) {
        int p = i / 192, c = i - p * 192;
        float v = xs[p * 193 + c];
        size_t off = (size_t)(pix0 + p) * C_SZ + c;
        g_xres[off] = v;
        g_xln[off]  = __float2bfloat16((v - smu[p]) * srs[p] * w[c] + b[c]);
    }
}

// ===================== high-throughput GEMM: 128(M) x 96(N) tile, 3-stage pipeline =========
// A [M,K] bf16 row-major, W [N,K] bf16 row-major. One __syncthreads per K=32 step.
// MODE 0: bf16 out [M,N]
// MODE 1: GELU -> bf16 out [M,N]
// MODE 3: outBCHW = res[m*192+n] + v (fp32, coalesced along tokens)
template<int MODE, int K>
__global__ __launch_bounds__(256, 2) void gemm_t(const __nv_bfloat16* __restrict__ A,
                                                 const __nv_bfloat16* __restrict__ W,
                                                 const float* __restrict__ bias,
                                                 int N, void* __restrict__ outp,
                                                 const float* __restrict__ res) {
    extern __shared__ unsigned char dsm[];
    constexpr int STG = (128 + 96) * 40 * 2;   // 17920 B per stage
    constexpr int NST = K / 32;
    float* sBias = (float*)(dsm + 3 * STG);

    const int tid = threadIdx.x, warp = tid >> 5, lane = tid & 31;
    const int wm = warp >> 1, wn = warp & 1;
    const int m0 = blockIdx.y * 128, n0 = blockIdx.x * 96;

    if (tid < 96) sBias[tid] = bias[n0 + tid];

    wmma::fragment<wmma::accumulator, 16, 16, 16, float> acc[2][3];
    #pragma unroll
    for (int i = 0; i < 2; i++)
        #pragma unroll
        for (int j = 0; j < 3; j++) wmma::fill_fragment(acc[i][j], 0.f);

    auto load_stage = [&](int buf, int kk) {
        __nv_bfloat16* As = (__nv_bfloat16*)(dsm + buf * STG);
        __nv_bfloat16* Bs = As + 128 * 40;
        int row = tid >> 2, q = tid & 3;
        cp16(As + row * 40 + q * 8,        A + (size_t)(m0 + row) * K + kk + q * 8);
        cp16(As + (row + 64) * 40 + q * 8, A + (size_t)(m0 + row + 64) * K + kk + q * 8);
        cp16(Bs + row * 40 + q * 8,        W + (size_t)(n0 + row) * K + kk + q * 8);
        if (tid < 128)
            cp16(Bs + (row + 64) * 40 + q * 8, W + (size_t)(n0 + row + 64) * K + kk + q * 8);
    };

    load_stage(0, 0);  CP_COMMIT;
    load_stage(1, 32); CP_COMMIT;

    #pragma unroll 1
    for (int s = 0; s < NST; s++) {
        if (s + 1 < NST) { CP_WAIT(1); } else { CP_WAIT(0); }
        __syncthreads();
        const __nv_bfloat16* As = (const __nv_bfloat16*)(dsm + (s % 3) * STG);
        const __nv_bfloat16* Bs = As + 128 * 40;
        #pragma unroll
        for (int ksub = 0; ksub < 2; ksub++) {
            wmma::fragment<wmma::matrix_a, 16, 16, 16, __nv_bfloat16, wmma::row_major> fa0, fa1;
            wmma::load_matrix_sync(fa0, As + (wm * 32) * 40 + ksub * 16, 40);
            wmma::load_matrix_sync(fa1, As + (wm * 32 + 16) * 40 + ksub * 16, 40);
            #pragma unroll
            for (int j = 0; j < 3; j++) {
                wmma::fragment<wmma::matrix_b, 16, 16, 16, __nv_bfloat16, wmma::col_major> fb;
                wmma::load_matrix_sync(fb, Bs + (wn * 48 + j * 16) * 40 + ksub * 16, 40);
                wmma::mma_sync(acc[0][j], fa0, fb, acc[0][j]);
                wmma::mma_sync(acc[1][j], fa1, fb, acc[1][j]);
            }
        }
        if (s + 2 < NST) { load_stage((s + 2) % 3, (s + 2) * 32); CP_COMMIT; }
    }
    __syncthreads();

    // epilogue: per warp 16x48 at a time
    float* Ep = (float*)dsm + warp * 832;        // 16 x 52
    const int cbase = n0 + wn * 48;
    #pragma unroll
    for (int h2 = 0; h2 < 2; h2++) {
        wmma::store_matrix_sync(Ep,      acc[h2][0], 52, wmma::mem_row_major);
        wmma::store_matrix_sync(Ep + 16, acc[h2][1], 52, wmma::mem_row_major);
        wmma::store_matrix_sync(Ep + 32, acc[h2][2], 52, wmma::mem_row_major);
        __syncwarp();
        if (MODE == 0 || MODE == 1) {
            #pragma unroll
            for (int e = 0; e < 24; e++) {
                int idx = lane + e * 32;
                int r = idx / 48, c = idx - r * 48;
                float v = Ep[r * 52 + c] + sBias[wn * 48 + c];
                if (MODE == 1) v = 0.5f * v * (1.f + erff(v * 0.70710678118654752f));
                ((__nv_bfloat16*)outp)[(size_t)(m0 + wm * 32 + h2 * 16 + r) * N + cbase + c] =
                    __float2bfloat16(v);
            }
        } else {
            #pragma unroll
            for (int e = 0; e < 24; e++) {
                int idx = lane + e * 32;
                int r = idx / 48, c = idx - r * 48;
                int m = m0 + wm * 32 + h2 * 16 + r;
                Ep[r * 52 + c] += sBias[wn * 48 + c] + res[(size_t)m * 192 + cbase + c];
            }
            __syncwarp();
            int rr = lane & 15;
            int cb2 = (lane >> 4) * 24;
            int m = m0 + wm * 32 + h2 * 16 + rr;
            size_t pixb = (size_t)(m >> 16) * 192 * 65536 + (size_t)(m & 65535);
            #pragma unroll
            for (int cc = 0; cc < 24; cc++) {
                int nn = cbase + cb2 + cc;
                ((float*)outp)[pixb + (size_t)nn * 65536] = Ep[rr * 52 + cb2 + cc];
            }
        }
        __syncwarp();
    }
}

// ===================== mega-lite: attention + proj + residual + LN2 per window ===========
// smem: XL @0 (64x200 bf16, attn_out), QK @25600 (64x584 bf16; later PO 64x200 f32),
//       R3 @100352 (Sf 2x64x68 f32 + Pm 2x64x64 bf16 | proj Bst 2x192x40 bf16),
//       BIAS @151552 (PB 192f, MU 64f, RS 64f)
#define XL_OFF   0
#define QK_OFF   25600
#define R3_OFF   100352
#define BIAS_OFF 151552
#define SMEM_TOT 152832

__global__ __launch_bounds__(256) void mega_lite(const float* __restrict__ projb,
                                                 const float* __restrict__ n2w,
                                                 const float* __restrict__ n2b) {
    extern __shared__ unsigned char smem[];
    __nv_bfloat16* XL = (__nv_bfloat16*)(smem + XL_OFF);
    __nv_bfloat16* QK = (__nv_bfloat16*)(smem + QK_OFF);
    float*         PO = (float*)(smem + QK_OFF);
    float* PB = (float*)(smem + BIAS_OFF);
    float* MU = PB + 192;
    float* RS = MU + 64;

    const int tid  = threadIdx.x;
    const int warp = tid >> 5, lane = tid & 31;
    const int win = blockIdx.x;
    const int b  = win >> 10;
    const int wh = (win >> 5) & 31;
    const int ww = win & 31;
    const int pixbase = b * 65536 + (wh * 8) * 256 + ww * 8;

    // load QKV tile (64 tokens x 576 ch) + proj bias
    if (tid < 192) PB[tid] = projb[tid];
    #pragma unroll
    for (int i = 0; i < 18; i++) {
        int u = tid + i * 256;        // 0..4607
        int t = u / 72, q = u - t * 72;
        int pix = pixbase + (t >> 3) * 256 + (t & 7);
        cp16(QK + t * 584 + q * 8, g_qkv + (size_t)pix * 576 + q * 8);
    }
    CP_COMMIT; CP_WAIT(0);
    __syncthreads();

    // ---- attention: 2 heads per iteration ----
    for (int p2 = 0; p2 < 3; p2++) {
        const int side = warp >> 2, wr = warp & 3;
        const int h = p2 * 2 + side;
        float* Sf = (float*)(smem + R3_OFF) + side * 4352;
        __nv_bfloat16* Pm = (__nv_bfloat16*)(smem + R3_OFF + 34816) + side * 4096;

        {
            wmma::fragment<wmma::accumulator, 16, 16, 16, float> s4[4];
            #pragma unroll
            for (int t = 0; t < 4; t++) wmma::fill_fragment(s4[t], 0.f);
            #pragma unroll
            for (int kk = 0; kk < 2; kk++) {
                wmma::fragment<wmma::matrix_a, 16, 16, 16, __nv_bfloat16, wmma::row_major> fq;
                wmma::load_matrix_sync(fq, QK + (wr * 16) * 584 + h * 32 + kk * 16, 584);
                #pragma unroll
                for (int mt = 0; mt < 4; mt++) {
                    wmma::fragment<wmma::matrix_b, 16, 16, 16, __nv_bfloat16, wmma::col_major> fk;
                    wmma::load_matrix_sync(fk, QK + (mt * 16) * 584 + 192 + h * 32 + kk * 16, 584);
                    wmma::mma_sync(s4[mt], fq, fk, s4[mt]);
                }
            }
            #pragma unroll
            for (int mt = 0; mt < 4; mt++)
                wmma::store_matrix_sync(Sf + (wr * 16) * 68 + mt * 16, s4[mt], 68, wmma::mem_row_major);
        }
        __syncthreads();

        {
            int st = tid >> 7;
            float* Sft = (float*)(smem + R3_OFF) + st * 4352;
            __nv_bfloat16* Pt = (__nv_bfloat16*)(smem + R3_OFF + 34816) + st * 4096;
            int row = (tid & 127) >> 1, hf = tid & 1;
            float* Sr = Sft + row * 68 + hf * 32;
            float mx = -1e30f;
            #pragma unroll
            for (int c = 0; c < 32; c++) mx = fmaxf(mx, Sr[c]);
            mx = fmaxf(mx, __shfl_xor_sync(0xffffffffu, mx, 1));
            float ev[32], sum = 0.f;
            #pragma unroll
            for (int c = 0; c < 32; c++) {
                ev[c] = __expf((Sr[c] - mx) * 0.17677669529663687f);
                sum += ev[c];
            }
            sum += __shfl_xor_sync(0xffffffffu, sum, 1);
            float inv = 1.f / sum;
            #pragma unroll
            for (int c = 0; c < 32; c++)
                Pt[row * 64 + hf * 32 + c] = __float2bfloat16(ev[c] * inv);
        }
        __syncthreads();

        {
            const int side2 = warp >> 2, wr2 = warp & 3;
            const int h2 = p2 * 2 + side2;
            __nv_bfloat16* Pm2 = (__nv_bfloat16*)(smem + R3_OFF + 34816) + side2 * 4096;
            wmma::fragment<wmma::accumulator, 16, 16, 16, float> o0, o1;
            wmma::fill_fragment(o0, 0.f); wmma::fill_fragment(o1, 0.f);
            #pragma unroll
            for (int kk = 0; kk < 4; kk++) {
                wmma::fragment<wmma::matrix_a, 16, 16, 16, __nv_bfloat16, wmma::row_major> fp;
                wmma::load_matrix_sync(fp, Pm2 + (wr2 * 16) * 64 + kk * 16, 64);
                wmma::fragment<wmma::matrix_b, 16, 16, 16, __nv_bfloat16, wmma::row_major> fv0, fv1;
                wmma::load_matrix_sync(fv0, QK + (kk * 16) * 584 + 384 + h2 * 32, 584);
                wmma::load_matrix_sync(fv1, QK + (kk * 16) * 584 + 384 + h2 * 32 + 16, 584);
                wmma::mma_sync(o0, fp, fv0, o0);
                wmma::mma_sync(o1, fp, fv1, o1);
            }
            float* stg = (float*)(smem + R3_OFF) + side2 * 4352 + wr2 * 512;  // 16x32
            wmma::store_matrix_sync(stg,      o0, 32, wmma::mem_row_major);
            wmma::store_matrix_sync(stg + 16, o1, 32, wmma::mem_row_major);
            __syncwarp();
            #pragma unroll
            for (int e = 0; e < 16; e++) {
                int idx = lane + e * 32;
                int r = idx >> 5, cc = idx & 31;
                XL[(wr2 * 16 + r) * 200 + h2 * 32 + cc] = __float2bfloat16(stg[r * 32 + cc]);
            }
        }
        __syncthreads();
    }

    // ---- proj = attn_out @ Wp^T -> PO (overwrites QK region) ----
    {
        __nv_bfloat16* Bst = (__nv_bfloat16*)(smem + R3_OFF);   // 2 x 192x40
        const int ms = warp & 3, nh = warp >> 2;
        wmma::fragment<wmma::accumulator, 16, 16, 16, float> pa[6];
        #pragma unroll
        for (int t = 0; t < 6; t++) wmma::fill_fragment(pa[t], 0.f);

        auto stagep = [&](int st, int k0) {
            #pragma unroll
            for (int i = 0; i < 3; i++) {
                int ch = tid + i * 256;     // 0..767
                int row = ch >> 2, q = ch & 3;
                cp16(Bst + st * 7680 + row * 40 + q * 8, g_wp + (size_t)row * 192 + k0 + q * 8);
            }
        };
        stagep(0, 0); CP_COMMIT;
        #pragma unroll 1
        for (int ks = 0; ks < 6; ks++) {
            if (ks < 5) { stagep((ks + 1) & 1, (ks + 1) * 32); CP_COMMIT; CP_WAIT(1); }
            else        { CP_WAIT(0); }
            __syncthreads();
            const __nv_bfloat16* bb = Bst + (ks & 1) * 7680;
            #pragma unroll
            for (int ksub = 0; ksub < 2; ksub++) {
                wmma::fragment<wmma::matrix_a, 16, 16, 16, __nv_bfloat16, wmma::row_major> fa;
                wmma::load_matrix_sync(fa, XL + (ms * 16) * 200 + ks * 32 + ksub * 16, 200);
                #pragma unroll
                for (int t = 0; t < 6; t++) {
                    wmma::fragment<wmma::matrix_b, 16, 16, 16, __nv_bfloat16, wmma::col_major> fb;
                    wmma::load_matrix_sync(fb, bb + (nh * 96 + t * 16) * 40 + ksub * 16, 40);
                    wmma::mma_sync(pa[t], fa, fb, pa[t]);
                }
            }
            __syncthreads();
        }
        #pragma unroll
        for (int t = 0; t < 6; t++)
            wmma::store_matrix_sync(PO + (ms * 16) * 200 + nh * 96 + t * 16, pa[t], 200, wmma::mem_row_major);
    }
    __syncthreads();

    // ---- residual (token-major g_xres) + bias ----
    #pragma unroll
    for (int i = 0; i < 48; i++) {
        int e = i * 256 + tid;
        int p = e / 192, c = e - p * 192;
        int pix = pixbase + (p >> 3) * 256 + (p & 7);
        PO[p * 200 + c] += g_xres[(size_t)pix * 192 + c] + PB[c];
    }
    __syncthreads();

    // ---- LN2 stats ----
    {
        int p = tid >> 2, q = tid & 3;
        float s = 0.f, sq = 0.f;
        #pragma unroll
        for (int j = 0; j < 48; j++) {
            float v = PO[p * 200 + q * 48 + j];
            s += v; sq += v * v;
        }
        s  += __shfl_xor_sync(0xffffffffu, s, 1);
        sq += __shfl_xor_sync(0xffffffffu, sq, 1);
        s  += __shfl_xor_sync(0xffffffffu, s, 2);
        sq += __shfl_xor_sync(0xffffffffu, sq, 2);
        if (q == 0) {
            float mu = s * (1.f / 192.f);
            MU[p] = mu;
            RS[p] = rsqrtf(sq * (1.f / 192.f) - mu * mu + 1e-5f);
        }
    }
    __syncthreads();

    // ---- write y1 + hln (token-major) ----
    #pragma unroll
    for (int i = 0; i < 48; i++) {
        int e = i * 256 + tid;
        int p = e / 192, c = e - p * 192;
        int pix = pixbase + (p >> 3) * 256 + (p & 7);
        float v = PO[p * 200 + c];
        g_y1[(size_t)pix * 192 + c] = v;
        g_hln[(size_t)pix * 192 + c] = __float2bfloat16((v - MU[p]) * RS[p] * n2w[c] + n2b[c]);
    }
}

extern "C" void kernel_launch(void* const* d_in, const int* in_sizes, int n_in,
                              void* d_out, int out_size) {
    const float* x     = (const float*)d_in[0];
    const float* n1w   = (const float*)d_in[1];
    const float* n1b   = (const float*)d_in[2];
    const float* qkvw  = (const float*)d_in[3];
    const float* qkvb  = (const float*)d_in[4];
    const float* projw = (const float*)d_in[5];
    const float* projb = (const float*)d_in[6];
    const float* n2w   = (const float*)d_in[7];
    const float* n2b   = (const float*)d_in[8];
    const float* w1    = (const float*)d_in[9];
    const float* b1    = (const float*)d_in[10];
    const float* w2    = (const float*)d_in[11];
    const float* b2    = (const float*)d_in[12];
    float* out = (float*)d_out;

    void *p_xln, *p_qkv, *p_y1, *p_hln, *p_hid, *p_wq, *p_w1, *p_w2;
    cudaGetSymbolAddress(&p_xln, g_xln);
    cudaGetSymbolAddress(&p_qkv, g_qkv);
    cudaGetSymbolAddress(&p_y1, g_y1);
    cudaGetSymbolAddress(&p_hln, g_hln);
    cudaGetSymbolAddress(&p_hid, g_hid);
    cudaGetSymbolAddress(&p_wq, g_wq);
    cudaGetSymbolAddress(&p_w1, g_w1);
    cudaGetSymbolAddress(&p_w2, g_w2);

    const int GSM = 3 * 17920 + 96 * 4;   // 54144
    static bool attr_done = false;
    if (!attr_done) {
        cudaFuncSetAttribute(gemm_t<0,192>, cudaFuncAttributeMaxDynamicSharedMemorySize, GSM);
        cudaFuncSetAttribute(gemm_t<1,192>, cudaFuncAttributeMaxDynamicSharedMemorySize, GSM);
        cudaFuncSetAttribute(gemm_t<3,768>, cudaFuncAttributeMaxDynamicSharedMemorySize, GSM);
        cudaFuncSetAttribute(mega_lite, cudaFuncAttributeMaxDynamicSharedMemorySize, SMEM_TOT);
        attr_done = true;
    }

    // weight convert (one kernel)
    cvt_all<<<1728, 256>>>(qkvw, projw, w1, w2);

    // LN1 -> g_xln (bf16) + g_xres (fp32), token-major raster order
    ln1_kernel<<<TOK/32, 256>>>(x, n1w, n1b);

    // QKV GEMM: [TOK,192] @ [576,192]^T -> g_qkv
    gemm_t<0,192><<<dim3(6, TOK/128), 256, GSM>>>((const __nv_bfloat16*)p_xln,
                                                  (const __nv_bfloat16*)p_wq,
                                                  qkvb, 576, p_qkv, nullptr);

    // attention + proj + residual + LN2 per window
    mega_lite<<<NWIN, 256, SMEM_TOT>>>(projb, n2w, n2b);

    // MLP1 + GELU: [TOK,192] @ [768,192]^T -> g_hid
    gemm_t<1,192><<<dim3(8, TOK/128), 256, GSM>>>((const __nv_bfloat16*)p_hln,
                                                  (const __nv_bfloat16*)p_w1,
                                                  b1, 768, p_hid, nullptr);

    // MLP2 + residual -> BCHW output
    gemm_t<3,768><<<dim3(2, TOK/128), 256, GSM>>>((const __nv_bfloat16*)p_hid,
                                                  (const __nv_bfloat16*)p_w2,
                                                  b2, 192, out, (const float*)p_y1);
}

// round 5
// speedup vs baseline: 2.6462x; 1.1622x over previous
#include <cuda_runtime.h>
#include <cuda_bf16.h>
#include <mma.h>

using namespace nvcuda;

#define C_SZ   192
#define TOK    262144
#define NWIN   4096
#define HID_SZ 768

// -------- scratch (device globals) --------
__device__ __nv_bfloat16 g_xln [(size_t)TOK * C_SZ];
__device__ float         g_xres[(size_t)TOK * C_SZ];
__device__ __nv_bfloat16 g_qkv [(size_t)TOK * 3 * C_SZ];
__device__ float         g_y1  [(size_t)TOK * C_SZ];
__device__ __nv_bfloat16 g_hln [(size_t)TOK * C_SZ];
__device__ __nv_bfloat16 g_hid [(size_t)TOK * HID_SZ];
__device__ __nv_bfloat16 g_wq  [3 * C_SZ * C_SZ];
__device__ __nv_bfloat16 g_wp  [C_SZ * C_SZ];
__device__ __nv_bfloat16 g_w1  [HID_SZ * C_SZ];
__device__ __nv_bfloat16 g_w2  [C_SZ * HID_SZ];

// -------- helpers --------
__device__ __forceinline__ unsigned smem_u32(const void* p) {
    return (unsigned)__cvta_generic_to_shared(p);
}
__device__ __forceinline__ void cp16(void* s, const void* g) {
    asm volatile("cp.async.cg.shared.global [%0], [%1], 16;\n"
                 :: "r"(smem_u32(s)), "l"(g));
}
#define CP_COMMIT asm volatile("cp.async.commit_group;\n" ::: "memory")
#define CP_WAIT(N) asm volatile("cp.async.wait_group %0;\n" :: "n"(N) : "memory")

// -------- fused weight convert --------
__global__ void cvt_all(const float* __restrict__ a, const float* __restrict__ b,
                        const float* __restrict__ c, const float* __restrict__ d) {
    int i = blockIdx.x * 256 + threadIdx.x;
    if (i < 110592)       g_wq[i]          = __float2bfloat16(a[i]);
    else if (i < 147456)  g_wp[i - 110592] = __float2bfloat16(b[i - 110592]);
    else if (i < 294912)  g_w1[i - 147456] = __float2bfloat16(c[i - 147456]);
    else if (i < 442368)  g_w2[i - 294912] = __float2bfloat16(d[i - 294912]);
}

// -------- LN1: single pass over x (BCHW) -> token-major g_xln (bf16) + g_xres (fp32)
__global__ __launch_bounds__(256) void ln1_kernel(const float* __restrict__ x,
                                                  const float* __restrict__ w,
                                                  const float* __restrict__ b) {
    __shared__ float xs[32 * 193];
    __shared__ float smu[32], srs[32];
    const int tid = threadIdx.x;
    const int pix0 = blockIdx.x * 32;
    const int bidx = pix0 >> 16;
    const int hw0  = pix0 & 65535;
    const float* xb = x + (size_t)bidx * C_SZ * 65536 + hw0;

    #pragma unroll 6
    for (int i = tid; i < 32 * 192; i += 256) {
        int c = i >> 5, p = i & 31;
        xs[p * 193 + c] = xb[(size_t)c * 65536 + p];
    }
    __syncthreads();

    if (tid < 64) {
        int t = tid >> 1, h = tid & 1;
        const float* row = xs + t * 193 + h * 96;
        float s = 0.f, sq = 0.f;
        #pragma unroll 8
        for (int j = 0; j < 96; j++) { float v = row[j]; s += v; sq += v * v; }
        s  += __shfl_xor_sync(0xffffffffu, s, 1);
        sq += __shfl_xor_sync(0xffffffffu, sq, 1);
        if (h == 0) {
            float mu = s * (1.f / C_SZ);
            smu[t] = mu;
            srs[t] = rsqrtf(sq * (1.f / C_SZ) - mu * mu + 1e-5f);
        }
    }
    __syncthreads();

    #pragma unroll 6
    for (int i = tid; i < 32 * 192; i += 256) {
        int p = i / 192, c = i - p * 192;
        float v = xs[p * 193 + c];
        size_t off = (size_t)(pix0 + p) * C_SZ + c;
        g_xres[off] = v;
        g_xln[off]  = __float2bfloat16((v - smu[p]) * srs[p] * w[c] + b[c]);
    }
}

// ===================== GEMM: 128(M) x 96(N) tile, K-step 64, 3-stage pipeline =========
// A [M,K] bf16 row-major, W [N,K] bf16 row-major. One __syncthreads per K=64 step.
// MODE 0: bf16 out [M,N]
// MODE 1: GELU -> bf16 out [M,N]
// MODE 3: outBCHW = res[m*192+n] + v (fp32)
template<int MODE, int K>
__global__ __launch_bounds__(256, 2) void gemm_t(const __nv_bfloat16* __restrict__ A,
                                                 const __nv_bfloat16* __restrict__ W,
                                                 const float* __restrict__ bias,
                                                 int N, void* __restrict__ outp,
                                                 const float* __restrict__ res) {
    extern __shared__ unsigned char dsm[];
    constexpr int STG = 224 * 72 * 2;   // 32256 B per stage (A 128 rows + B 96 rows, 64+8 pad)
    constexpr int NST = K / 64;
    float* sBias = (float*)(dsm + 3 * STG);

    const int tid = threadIdx.x, warp = tid >> 5, lane = tid & 31;
    const int wm = warp >> 1, wn = warp & 1;
    const int m0 = blockIdx.y * 128, n0 = blockIdx.x * 96;

    if (tid < 96) sBias[tid] = bias[n0 + tid];

    wmma::fragment<wmma::accumulator, 16, 16, 16, float> acc[2][3];
    #pragma unroll
    for (int i = 0; i < 2; i++)
        #pragma unroll
        for (int j = 0; j < 3; j++) wmma::fill_fragment(acc[i][j], 0.f);

    auto load_stage = [&](int buf, int kk) {
        __nv_bfloat16* st = (__nv_bfloat16*)(dsm + buf * STG);
        #pragma unroll
        for (int i = 0; i < 7; i++) {
            int u = tid + i * 256;       // 0..1791
            int row = u >> 3, q = u & 7;
            const __nv_bfloat16* src = (row < 128)
                ? A + (size_t)(m0 + row) * K + kk + q * 8
                : W + (size_t)(n0 + row - 128) * K + kk + q * 8;
            cp16(st + row * 72 + q * 8, src);
        }
    };

    load_stage(0, 0);  CP_COMMIT;
    if (NST > 1) { load_stage(1, 64); CP_COMMIT; }

    #pragma unroll 1
    for (int s = 0; s < NST; s++) {
        if (s + 1 < NST) { CP_WAIT(1); } else { CP_WAIT(0); }
        __syncthreads();
        const __nv_bfloat16* As = (const __nv_bfloat16*)(dsm + (s % 3) * STG);
        const __nv_bfloat16* Bs = As + 128 * 72;
        #pragma unroll
        for (int ksub = 0; ksub < 4; ksub++) {
            wmma::fragment<wmma::matrix_a, 16, 16, 16, __nv_bfloat16, wmma::row_major> fa0, fa1;
            wmma::load_matrix_sync(fa0, As + (wm * 32) * 72 + ksub * 16, 72);
            wmma::load_matrix_sync(fa1, As + (wm * 32 + 16) * 72 + ksub * 16, 72);
            #pragma unroll
            for (int j = 0; j < 3; j++) {
                wmma::fragment<wmma::matrix_b, 16, 16, 16, __nv_bfloat16, wmma::col_major> fb;
                wmma::load_matrix_sync(fb, Bs + (wn * 48 + j * 16) * 72 + ksub * 16, 72);
                wmma::mma_sync(acc[0][j], fa0, fb, acc[0][j]);
                wmma::mma_sync(acc[1][j], fa1, fb, acc[1][j]);
            }
        }
        if (s + 2 < NST) { load_stage((s + 2) % 3, (s + 2) * 64); CP_COMMIT; }
    }
    __syncthreads();

    // epilogue: per warp 16x48 at a time
    float* Ep = (float*)dsm + warp * 832;        // 16 x 52
    const int cbase = n0 + wn * 48;
    #pragma unroll
    for (int h2 = 0; h2 < 2; h2++) {
        wmma::store_matrix_sync(Ep,      acc[h2][0], 52, wmma::mem_row_major);
        wmma::store_matrix_sync(Ep + 16, acc[h2][1], 52, wmma::mem_row_major);
        wmma::store_matrix_sync(Ep + 32, acc[h2][2], 52, wmma::mem_row_major);
        __syncwarp();
        if (MODE == 0 || MODE == 1) {
            #pragma unroll
            for (int e = 0; e < 24; e++) {
                int idx = lane + e * 32;
                int r = idx / 48, c = idx - r * 48;
                float v = Ep[r * 52 + c] + sBias[wn * 48 + c];
                if (MODE == 1) v = 0.5f * v * (1.f + erff(v * 0.70710678118654752f));
                ((__nv_bfloat16*)outp)[(size_t)(m0 + wm * 32 + h2 * 16 + r) * N + cbase + c] =
                    __float2bfloat16(v);
            }
        } else {
            #pragma unroll
            for (int e = 0; e < 24; e++) {
                int idx = lane + e * 32;
                int r = idx / 48, c = idx - r * 48;
                int m = m0 + wm * 32 + h2 * 16 + r;
                Ep[r * 52 + c] += sBias[wn * 48 + c] + res[(size_t)m * 192 + cbase + c];
            }
            __syncwarp();
            int rr = lane & 15;
            int cb2 = (lane >> 4) * 24;
            int m = m0 + wm * 32 + h2 * 16 + rr;
            size_t pixb = (size_t)(m >> 16) * 192 * 65536 + (size_t)(m & 65535);
            #pragma unroll
            for (int cc = 0; cc < 24; cc++) {
                int nn = cbase + cb2 + cc;
                ((float*)outp)[pixb + (size_t)nn * 65536] = Ep[rr * 52 + cb2 + cc];
            }
        }
        __syncwarp();
    }
}

// ===================== mega-lite v2: attention (streamed heads) + proj + residual + LN2 ======
// smem layout (bytes), total 88320 -> 2 CTAs/SM:
//   XL  @ 0     : 64x200 bf16 (25600)  attn output
//   SLC @ 25600 : 2 sides x 64x104 bf16 (26624)  per-head-pair Q|K|V slice; Q|K cols reused as P
//   SF  @ 52224 : 2 sides x 64x68 f32 (34816)    scores; proj weight stages; PV staging
//   (PO: proj output 64x200 f32 overlays SLC+SF after attention)
//   BIAS@ 87040 : PB 192f + MU 64f + RS 64f
#define XL_OFF   0
#define SLC_OFF  25600
#define SF_OFF   52224
#define BIAS_OFF 87040
#define MEGA_SMEM 88320

__global__ __launch_bounds__(256, 2) void mega_lite(const float* __restrict__ projb,
                                                    const float* __restrict__ n2w,
                                                    const float* __restrict__ n2b) {
    extern __shared__ unsigned char smem[];
    __nv_bfloat16* XL  = (__nv_bfloat16*)(smem + XL_OFF);
    __nv_bfloat16* SLC = (__nv_bfloat16*)(smem + SLC_OFF);
    float*         SF  = (float*)(smem + SF_OFF);
    float*         PO  = (float*)(smem + SLC_OFF);    // 64x200 f32 overlay (post-attention)
    float* PB = (float*)(smem + BIAS_OFF);
    float* MU = PB + 192;
    float* RS = MU + 64;

    const int tid  = threadIdx.x;
    const int warp = tid >> 5, lane = tid & 31;
    const int win = blockIdx.x;
    const int b  = win >> 10;
    const int wh = (win >> 5) & 31;
    const int ww = win & 31;
    const int pixbase = b * 65536 + (wh * 8) * 256 + ww * 8;

    if (tid < 192) PB[tid] = projb[tid];

    const int side = warp >> 2, wr = warp & 3;

    // ---- attention: 3 iterations of 2 heads (one per side) ----
    for (int p2 = 0; p2 < 3; p2++) {
        // load Q|K|V slice for heads (2*p2, 2*p2+1): per side 64 tokens x 96 ch, stride 104
        #pragma unroll
        for (int i = 0; i < 6; i++) {
            int u = tid + i * 256;        // 0..1535
            int sd = u >= 768;
            int v = u - sd * 768;
            int t = v / 12, j = v - t * 12;
            int mat = j >> 2, q4 = j & 3;
            int h = p2 * 2 + sd;
            int pix = pixbase + (t >> 3) * 256 + (t & 7);
            cp16(SLC + sd * 6656 + t * 104 + mat * 32 + q4 * 8,
                 g_qkv + (size_t)pix * 576 + mat * 192 + h * 32 + q4 * 8);
        }
        CP_COMMIT; CP_WAIT(0);
        __syncthreads();

        const __nv_bfloat16* Qs = SLC + side * 6656;        // cols 0..32
        const __nv_bfloat16* Ks = Qs + 32;                  // cols 32..64
        const __nv_bfloat16* Vs = Qs + 64;                  // cols 64..96
        float* Sf = SF + side * 4352;                       // 64x68

        // S = Q @ K^T
        {
            wmma::fragment<wmma::accumulator, 16, 16, 16, float> s4[4];
            #pragma unroll
            for (int t = 0; t < 4; t++) wmma::fill_fragment(s4[t], 0.f);
            #pragma unroll
            for (int kk = 0; kk < 2; kk++) {
                wmma::fragment<wmma::matrix_a, 16, 16, 16, __nv_bfloat16, wmma::row_major> fq;
                wmma::load_matrix_sync(fq, Qs + (wr * 16) * 104 + kk * 16, 104);
                #pragma unroll
                for (int mt = 0; mt < 4; mt++) {
                    wmma::fragment<wmma::matrix_b, 16, 16, 16, __nv_bfloat16, wmma::col_major> fk;
                    wmma::load_matrix_sync(fk, Ks + (mt * 16) * 104 + kk * 16, 104);
                    wmma::mma_sync(s4[mt], fq, fk, s4[mt]);
                }
            }
            #pragma unroll
            for (int mt = 0; mt < 4; mt++)
                wmma::store_matrix_sync(Sf + (wr * 16) * 68 + mt * 16, s4[mt], 68, wmma::mem_row_major);
        }
        __syncthreads();

        // softmax: P (bf16) written over dead Q|K columns of the slice
        {
            int sd = tid >> 7;
            int row = (tid & 127) >> 1, hf = tid & 1;
            float* Sr = SF + sd * 4352 + row * 68 + hf * 32;
            __nv_bfloat16* Pr = SLC + sd * 6656 + row * 104 + hf * 32;
            float mx = -1e30f;
            #pragma unroll
            for (int c = 0; c < 32; c++) mx = fmaxf(mx, Sr[c]);
            mx = fmaxf(mx, __shfl_xor_sync(0xffffffffu, mx, 1));
            float sum = 0.f;
            #pragma unroll
            for (int c = 0; c < 32; c++) {
                float e = __expf((Sr[c] - mx) * 0.17677669529663687f);
                Sr[c] = e; sum += e;
            }
            sum += __shfl_xor_sync(0xffffffffu, sum, 1);
            float inv = 1.f / sum;
            #pragma unroll
            for (int c = 0; c < 32; c++)
                Pr[c] = __float2bfloat16(Sr[c] * inv);
        }
        __syncthreads();

        // O = P @ V -> XL cols h*32..h*32+32
        {
            const int h = p2 * 2 + side;
            const __nv_bfloat16* Pm = SLC + side * 6656;    // 64x64, stride 104
            wmma::fragment<wmma::accumulator, 16, 16, 16, float> o0, o1;
            wmma::fill_fragment(o0, 0.f); wmma::fill_fragment(o1, 0.f);
            #pragma unroll
            for (int kk = 0; kk < 4; kk++) {
                wmma::fragment<wmma::matrix_a, 16, 16, 16, __nv_bfloat16, wmma::row_major> fp;
                wmma::load_matrix_sync(fp, Pm + (wr * 16) * 104 + kk * 16, 104);
                wmma::fragment<wmma::matrix_b, 16, 16, 16, __nv_bfloat16, wmma::row_major> fv0, fv1;
                wmma::load_matrix_sync(fv0, Vs + (kk * 16) * 104, 104);
                wmma::load_matrix_sync(fv1, Vs + (kk * 16) * 104 + 16, 104);
                wmma::mma_sync(o0, fp, fv0, o0);
                wmma::mma_sync(o1, fp, fv1, o1);
            }
            float* stg = SF + side * 4352 + wr * 512;       // 16x32
            wmma::store_matrix_sync(stg,      o0, 32, wmma::mem_row_major);
            wmma::store_matrix_sync(stg + 16, o1, 32, wmma::mem_row_major);
            __syncwarp();
            #pragma unroll
            for (int e = 0; e < 16; e++) {
                int idx = lane + e * 32;
                int r = idx >> 5, cc = idx & 31;
                XL[(wr * 16 + r) * 200 + h * 32 + cc] = __float2bfloat16(stg[r * 32 + cc]);
            }
        }
        __syncthreads();
    }

    // ---- proj = attn_out @ Wp^T -> PO fp32 [64][200] (overlays SLC+SF) ----
    {
        __nv_bfloat16* Bst = (__nv_bfloat16*)(smem + SF_OFF);   // 2 x 192x40 (30720 B)
        const int ms = warp & 3, nh = warp >> 2;
        wmma::fragment<wmma::accumulator, 16, 16, 16, float> pa[6];
        #pragma unroll
        for (int t = 0; t < 6; t++) wmma::fill_fragment(pa[t], 0.f);

        auto stagep = [&](int st, int k0) {
            #pragma unroll
            for (int i = 0; i < 3; i++) {
                int ch = tid + i * 256;     // 0..767
                int row = ch >> 2, q = ch & 3;
                cp16(Bst + st * 7680 + row * 40 + q * 8, g_wp + (size_t)row * 192 + k0 + q * 8);
            }
        };
        stagep(0, 0); CP_COMMIT;
        #pragma unroll 1
        for (int ks = 0; ks < 6; ks++) {
            if (ks < 5) { stagep((ks + 1) & 1, (ks + 1) * 32); CP_COMMIT; CP_WAIT(1); }
            else        { CP_WAIT(0); }
            __syncthreads();
            const __nv_bfloat16* bb = Bst + (ks & 1) * 7680;
            #pragma unroll
            for (int ksub = 0; ksub < 2; ksub++) {
                wmma::fragment<wmma::matrix_a, 16, 16, 16, __nv_bfloat16, wmma::row_major> fa;
                wmma::load_matrix_sync(fa, XL + (ms * 16) * 200 + ks * 32 + ksub * 16, 200);
                #pragma unroll
                for (int t = 0; t < 6; t++) {
                    wmma::fragment<wmma::matrix_b, 16, 16, 16, __nv_bfloat16, wmma::col_major> fb;
                    wmma::load_matrix_sync(fb, bb + (nh * 96 + t * 16) * 40 + ksub * 16, 40);
                    wmma::mma_sync(pa[t], fa, fb, pa[t]);
                }
            }
            __syncthreads();
        }
        #pragma unroll
        for (int t = 0; t < 6; t++)
            wmma::store_matrix_sync(PO + (ms * 16) * 200 + nh * 96 + t * 16, pa[t], 200, wmma::mem_row_major);
    }
    __syncthreads();

    // ---- residual (token-major g_xres) + bias ----
    #pragma unroll
    for (int i = 0; i < 48; i++) {
        int e = i * 256 + tid;
        int p = e / 192, c = e - p * 192;
        int pix = pixbase + (p >> 3) * 256 + (p & 7);
        PO[p * 200 + c] += g_xres[(size_t)pix * 192 + c] + PB[c];
    }
    __syncthreads();

    // ---- LN2 stats ----
    {
        int p = tid >> 2, q = tid & 3;
        float s = 0.f, sq = 0.f;
        #pragma unroll
        for (int j = 0; j < 48; j++) {
            float v = PO[p * 200 + q * 48 + j];
            s += v; sq += v * v;
        }
        s  += __shfl_xor_sync(0xffffffffu, s, 1);
        sq += __shfl_xor_sync(0xffffffffu, sq, 1);
        s  += __shfl_xor_sync(0xffffffffu, s, 2);
        sq += __shfl_xor_sync(0xffffffffu, sq, 2);
        if (q == 0) {
            float mu = s * (1.f / 192.f);
            MU[p] = mu;
            RS[p] = rsqrtf(sq * (1.f / 192.f) - mu * mu + 1e-5f);
        }
    }
    __syncthreads();

    // ---- write y1 + hln (token-major) ----
    #pragma unroll
    for (int i = 0; i < 48; i++) {
        int e = i * 256 + tid;
        int p = e / 192, c = e - p * 192;
        int pix = pixbase + (p >> 3) * 256 + (p & 7);
        float v = PO[p * 200 + c];
        g_y1[(size_t)pix * 192 + c] = v;
        g_hln[(size_t)pix * 192 + c] = __float2bfloat16((v - MU[p]) * RS[p] * n2w[c] + n2b[c]);
    }
}

extern "C" void kernel_launch(void* const* d_in, const int* in_sizes, int n_in,
                              void* d_out, int out_size) {
    const float* x     = (const float*)d_in[0];
    const float* n1w   = (const float*)d_in[1];
    const float* n1b   = (const float*)d_in[2];
    const float* qkvw  = (const float*)d_in[3];
    const float* qkvb  = (const float*)d_in[4];
    const float* projw = (const float*)d_in[5];
    const float* projb = (const float*)d_in[6];
    const float* n2w   = (const float*)d_in[7];
    const float* n2b   = (const float*)d_in[8];
    const float* w1    = (const float*)d_in[9];
    const float* b1    = (const float*)d_in[10];
    const float* w2    = (const float*)d_in[11];
    const float* b2    = (const float*)d_in[12];
    float* out = (float*)d_out;

    void *p_xln, *p_qkv, *p_y1, *p_hln, *p_hid, *p_wq, *p_w1, *p_w2;
    cudaGetSymbolAddress(&p_xln, g_xln);
    cudaGetSymbolAddress(&p_qkv, g_qkv);
    cudaGetSymbolAddress(&p_y1, g_y1);
    cudaGetSymbolAddress(&p_hln, g_hln);
    cudaGetSymbolAddress(&p_hid, g_hid);
    cudaGetSymbolAddress(&p_wq, g_wq);
    cudaGetSymbolAddress(&p_w1, g_w1);
    cudaGetSymbolAddress(&p_w2, g_w2);

    const int GSM = 3 * 32256 + 384;   // 97152
    static bool attr_done = false;
    if (!attr_done) {
        cudaFuncSetAttribute(gemm_t<0,192>, cudaFuncAttributeMaxDynamicSharedMemorySize, GSM);
        cudaFuncSetAttribute(gemm_t<1,192>, cudaFuncAttributeMaxDynamicSharedMemorySize, GSM);
        cudaFuncSetAttribute(gemm_t<3,768>, cudaFuncAttributeMaxDynamicSharedMemorySize, GSM);
        cudaFuncSetAttribute(mega_lite, cudaFuncAttributeMaxDynamicSharedMemorySize, MEGA_SMEM);
        attr_done = true;
    }

    // weight convert
    cvt_all<<<1728, 256>>>(qkvw, projw, w1, w2);

    // LN1 -> g_xln (bf16) + g_xres (fp32), token-major
    ln1_kernel<<<TOK/32, 256>>>(x, n1w, n1b);

    // QKV GEMM: [TOK,192] @ [576,192]^T -> g_qkv
    gemm_t<0,192><<<dim3(6, TOK/128), 256, GSM>>>((const __nv_bfloat16*)p_xln,
                                                  (const __nv_bfloat16*)p_wq,
                                                  qkvb, 576, p_qkv, nullptr);

    // attention + proj + residual + LN2 per window
    mega_lite<<<NWIN, 256, MEGA_SMEM>>>(projb, n2w, n2b);

    // MLP1 + GELU: [TOK,192] @ [768,192]^T -> g_hid
    gemm_t<1,192><<<dim3(8, TOK/128), 256, GSM>>>((const __nv_bfloat16*)p_hln,
                                                  (const __nv_bfloat16*)p_w1,
                                                  b1, 768, p_hid, nullptr);

    // MLP2 + residual -> BCHW output
    gemm_t<3,768><<<dim3(2, TOK/128), 256, GSM>>>((const __nv_bfloat16*)p_hid,
                                                  (const __nv_bfloat16*)p_w2,
                                                  b2, 192, out, (const float*)p_y1);
}